// round 14
// baseline (speedup 1.0000x reference)
#include <cuda_runtime.h>
#include <cuda_bf16.h>
#include <cstdint>
#include <stdint.h>
#include <math.h>

#define D_MODEL 512
#define NHEAD   8
#define DHEAD   64
#define NLAYER  8
#define FF_DIM  2048
#define VOCAB   32000
#define BATCH   2
#define SEQ     2048
#define M_ROWS  (BATCH*SEQ)   // 4096

// ---------------- scratch (static __device__ globals; no allocs allowed) ----
__device__ float g_h[M_ROWS * D_MODEL];                  // residual stream fp32

__device__ __nv_bfloat16 g_ahi[M_ROWS * D_MODEL];        // ln out / attn out
__device__ __nv_bfloat16 g_alo[M_ROWS * D_MODEL];
__device__ __nv_bfloat16 g_fhi[M_ROWS * FF_DIM];         // ff1 out
__device__ __nv_bfloat16 g_flo[M_ROWS * FF_DIM];

// q/k/vt packed: Q[BH,T,DH] @0, K[BH,T,DH] @2097152, Vt[BH,DH,T] @4194304
#define QK_KOFF 2097152
#define QK_VOFF 4194304
__device__ __nv_bfloat16 g_qkhi[6291456];
__device__ __nv_bfloat16 g_qklo[6291456];

// transposed weights, bf16 hi/lo.
#define W_LSTRIDE 3145728ULL
#define W_OFF_QKV 0ULL
#define W_OFF_AFC 786432ULL
#define W_OFF_FF1 1048576ULL
#define W_OFF_FF2 2097152ULL
#define W_OFF_FC  (8ULL * W_LSTRIDE)
#define W_TOTAL   (W_OFF_FC + 32000ULL * 512ULL)
__device__ __nv_bfloat16 g_whi[W_TOTAL];
__device__ __nv_bfloat16 g_wlo[W_TOTAL];

// ---------------- PTX helpers (sm_80-compatible only) ------------------------
__device__ __forceinline__ uint32_t smem_u32(const void* p) {
    uint32_t a;
    asm("{ .reg .u64 t; cvta.to.shared.u64 t, %1; cvt.u32.u64 %0, t; }"
        : "=r"(a) : "l"(p));
    return a;
}

__device__ __forceinline__ void cp_async16(uint32_t saddr, const void* gaddr) {
    asm volatile("cp.async.cg.shared.global [%0], [%1], 16;"
                 :: "r"(saddr), "l"(gaddr));
}

__device__ __forceinline__ void ldm_x4(uint32_t* r, uint32_t addr) {
    asm volatile("ldmatrix.sync.aligned.m8n8.x4.shared.b16 {%0,%1,%2,%3}, [%4];"
                 : "=r"(r[0]), "=r"(r[1]), "=r"(r[2]), "=r"(r[3]) : "r"(addr));
}

__device__ __forceinline__ void mma_bf16(float* c, const uint32_t* a, const uint32_t* b) {
    asm volatile(
        "mma.sync.aligned.m16n8k16.row.col.f32.bf16.bf16.f32 "
        "{%0,%1,%2,%3}, {%4,%5,%6,%7}, {%8,%9}, {%0,%1,%2,%3};"
        : "+f"(c[0]), "+f"(c[1]), "+f"(c[2]), "+f"(c[3])
        : "r"(a[0]), "r"(a[1]), "r"(a[2]), "r"(a[3]), "r"(b[0]), "r"(b[1]));
}

// pack two floats into bf16x2 hi reg + residual lo reg
__device__ __forceinline__ void split2(float x, float y, uint32_t& hi, uint32_t& lo) {
    __nv_bfloat16 hx = __float2bfloat16(x), hy = __float2bfloat16(y);
    __nv_bfloat162 H{hx, hy};
    __nv_bfloat162 L{__float2bfloat16(x - __bfloat162float(hx)),
                     __float2bfloat16(y - __bfloat162float(hy))};
    hi = *reinterpret_cast<uint32_t*>(&H);
    lo = *reinterpret_cast<uint32_t*>(&L);
}

// ---------------- embedding + positional encoding ---------------------------
__global__ void embed_kernel(const int* __restrict__ x,
                             const float* __restrict__ emb,
                             float* __restrict__ h)
{
    int row = blockIdx.x;
    int t   = row % SEQ;
    int tok = x[row];
    int i   = threadIdx.x;
    float f = expf((float)(2 * i) * (-9.210340371976184f / 512.0f));
    float ang = (float)t * f;
    float s, c;
    sincosf(ang, &s, &c);
    const float* e = emb + (size_t)tok * D_MODEL;
    float* hp = h + (size_t)row * D_MODEL;
    hp[2 * i]     = e[2 * i]     + s;
    hp[2 * i + 1] = e[2 * i + 1] + c;
}

// ---------------- layernorm -> bf16 hi/lo split ------------------------------
__global__ void ln_split_kernel(const float* __restrict__ x,
                                const float* __restrict__ scale,
                                const float* __restrict__ bias,
                                __nv_bfloat16* __restrict__ yhi,
                                __nv_bfloat16* __restrict__ ylo)
{
    int row = blockIdx.x;
    int tid = threadIdx.x;
    const float4* xr = (const float4*)(x + (size_t)row * D_MODEL);
    float4 v = xr[tid];
    float s  = v.x + v.y + v.z + v.w;
    float sq = v.x*v.x + v.y*v.y + v.z*v.z + v.w*v.w;
    #pragma unroll
    for (int o = 16; o > 0; o >>= 1) {
        s  += __shfl_xor_sync(0xffffffffu, s,  o);
        sq += __shfl_xor_sync(0xffffffffu, sq, o);
    }
    __shared__ float ss[4], ssq[4];
    int wid = tid >> 5, lane = tid & 31;
    if (lane == 0) { ss[wid] = s; ssq[wid] = sq; }
    __syncthreads();
    s  = ss[0]  + ss[1]  + ss[2]  + ss[3];
    sq = ssq[0] + ssq[1] + ssq[2] + ssq[3];
    float mu  = s * (1.0f / D_MODEL);
    float var = sq * (1.0f / D_MODEL) - mu * mu;
    float inv = rsqrtf(var + 1e-5f);
    float4 sc = ((const float4*)scale)[tid];
    float4 bi = ((const float4*)bias)[tid];
    float o0 = (v.x - mu) * inv * sc.x + bi.x;
    float o1 = (v.y - mu) * inv * sc.y + bi.y;
    float o2 = (v.z - mu) * inv * sc.z + bi.z;
    float o3 = (v.w - mu) * inv * sc.w + bi.w;
    uint32_t h0, l0, h1, l1;
    split2(o0, o1, h0, l0);
    split2(o2, o3, h1, l1);
    uint32_t* ph = (uint32_t*)(yhi + (size_t)row * D_MODEL);
    uint32_t* pl = (uint32_t*)(ylo + (size_t)row * D_MODEL);
    ph[tid*2] = h0; ph[tid*2+1] = h1;
    pl[tid*2] = l0; pl[tid*2+1] = l1;
}

// ---------------- weight transpose + split (batched over layers) -------------
// W[K,N] (fp32) -> Wt hi/lo [N,K] bf16.  64x64 tiles, 256 threads.
__global__ __launch_bounds__(256)
void wprep_kernel(const float* __restrict__ W,
                  __nv_bfloat16* __restrict__ hi,
                  __nv_bfloat16* __restrict__ lo,
                  int K, int N, size_t wstride, size_t ostride)
{
    __shared__ float t[64][65];
    const float* Wl = W + (size_t)blockIdx.z * wstride;
    int n0 = blockIdx.x * 64, k0 = blockIdx.y * 64;
    int tid = threadIdx.x;
    #pragma unroll
    for (int j = 0; j < 4; j++) {
        int idx = tid + j * 256;
        int kk = idx >> 4;
        int c4 = idx & 15;
        float4 v = *(const float4*)&Wl[(size_t)(k0 + kk) * N + n0 + c4 * 4];
        t[kk][c4*4+0] = v.x; t[kk][c4*4+1] = v.y;
        t[kk][c4*4+2] = v.z; t[kk][c4*4+3] = v.w;
    }
    __syncthreads();
    int tx = tid & 31, ty = tid >> 5;
    size_t obase = (size_t)blockIdx.z * ostride;
    #pragma unroll
    for (int j = 0; j < 8; j++) {
        int nl = ty + j * 8;
        float v0 = t[tx*2][nl], v1 = t[tx*2+1][nl];
        uint32_t h2, l2;
        split2(v0, v1, h2, l2);
        size_t o = obase + (size_t)(n0 + nl) * K + k0 + tx * 2;
        *(uint32_t*)(hi + o) = h2;
        *(uint32_t*)(lo + o) = l2;
    }
}

// ---------------- HMMA bf16x3 GEMM (256 thr, 8 warps 4x2, BM128xBN64) --------
// 2 CTAs/SM (96KB smem), 2-stage cp.async pipeline, ONE barrier per chunk
// (wait(0) -> sync -> issue(next) -> compute; WAR on alt stage guarded by the
// barrier one iteration earlier).  bm on blockIdx.x.
// mode 0: C fp32 = [res +] A@W + bias
// mode 1: Ohi/Olo bf16 = split(gelu(A@W + bias))
// mode 2: scatter q/k/vt hi/lo from A@W + bias
#define CHUNK_K 64
#define STAGE_BYTES 49152
#define T_AHI 0
#define T_ALO 16384
#define T_BHI 32768
#define T_BLO 40960
#define GEMM_SMEM (2*STAGE_BYTES)

__device__ __forceinline__ void store_qkv(int row, int col, float v0, float v1,
                                          __nv_bfloat16* Ohi, __nv_bfloat16* Olo)
{
    int sect = col >> 9;
    int hh = (col >> 6) & 7;
    int d = col & 63;
    int bb = row >> 11, tt = row & 2047;
    int bh = bb * 8 + hh;
    uint32_t hi, lo;
    split2(v0, v1, hi, lo);
    if (sect < 2) {
        size_t off = (size_t)sect * QK_KOFF + ((size_t)bh * 2048 + tt) * 64 + d;
        *(uint32_t*)(Ohi + off) = hi;
        *(uint32_t*)(Olo + off) = lo;
    } else {
        size_t off = QK_VOFF + ((size_t)bh * 64 + d) * 2048 + tt;
        __nv_bfloat162 H = *reinterpret_cast<__nv_bfloat162*>(&hi);
        __nv_bfloat162 L = *reinterpret_cast<__nv_bfloat162*>(&lo);
        Ohi[off] = H.x; Ohi[off + 2048] = H.y;
        Olo[off] = L.x; Olo[off + 2048] = L.y;
    }
}

__global__ __launch_bounds__(256, 2)
void gemm_tc(const __nv_bfloat16* __restrict__ Ahi, const __nv_bfloat16* __restrict__ Alo,
             const __nv_bfloat16* __restrict__ Bhi, const __nv_bfloat16* __restrict__ Blo,
             const float* __restrict__ bias, const float* __restrict__ res,
             float* __restrict__ C, __nv_bfloat16* __restrict__ Ohi,
             __nv_bfloat16* __restrict__ Olo, int M, int N, int K, int mode)
{
    extern __shared__ char smem[];
    uint32_t sb = smem_u32(smem);
    int tid = threadIdx.x, lane = tid & 31, wid = tid >> 5;
    int bm = blockIdx.x * 128, bn = blockIdx.y * 64;   // bm fast: L2 B-tile reuse
    int wm = wid >> 1, wn = wid & 1;       // 4 x 2 warp grid, warp tile 32x32

    float acc[2][4][4];
    #pragma unroll
    for (int i = 0; i < 2; i++)
        #pragma unroll
        for (int j = 0; j < 4; j++)
            #pragma unroll
            for (int k = 0; k < 4; k++) acc[i][j][k] = 0.0f;

    int nch = K / CHUNK_K;

    auto issue = [&](int c, int s) {
        uint32_t base = sb + s * STAGE_BYTES;
        int k0 = c * CHUNK_K;
        #pragma unroll
        for (int i = 0; i < 4; i++) {
            int idx = tid + i * 256;
            int r = idx >> 3, q = idx & 7;
            uint32_t off = (uint32_t)(r * 128 + q * 16);
            uint32_t sw  = off ^ ((off >> 3) & 0x70);
            cp_async16(base + T_AHI + sw, Ahi + (size_t)(bm + r) * K + k0 + q * 8);
            cp_async16(base + T_ALO + sw, Alo + (size_t)(bm + r) * K + k0 + q * 8);
        }
        #pragma unroll
        for (int i = 0; i < 2; i++) {
            int idx = tid + i * 256;
            int r = idx >> 3, q = idx & 7;
            uint32_t off = (uint32_t)(r * 128 + q * 16);
            uint32_t sw  = off ^ ((off >> 3) & 0x70);
            cp_async16(base + T_BHI + sw, Bhi + (size_t)(bn + r) * K + k0 + q * 8);
            cp_async16(base + T_BLO + sw, Blo + (size_t)(bn + r) * K + k0 + q * 8);
        }
        asm volatile("cp.async.commit_group;" ::: "memory");
    };

    issue(0, 0);
    for (int c = 0; c < nch; c++) {
        int s = c & 1;
        asm volatile("cp.async.wait_group 0;" ::: "memory");
        __syncthreads();
        if (c + 1 < nch) issue(c + 1, s ^ 1);

        uint32_t base = sb + s * STAGE_BYTES;
        int rowA  = wm * 32 + (lane & 15);
        int rowB  = wn * 32 + (lane & 7) + ((lane >> 4) << 3);
        #pragma unroll
        for (int ks = 0; ks < 4; ks++) {
            uint32_t ah[2][4], al[2][4], bh[4][2], bl[4][2];
            uint32_t colA = (uint32_t)(ks * 32 + ((lane >> 4) & 1) * 16);
            uint32_t colB = (uint32_t)(ks * 32 + ((lane >> 3) & 1) * 16);
            #pragma unroll
            for (int mt = 0; mt < 2; mt++) {
                uint32_t off = (uint32_t)((rowA + mt * 16) * 128) + colA;
                uint32_t sw  = off ^ ((off >> 3) & 0x70);
                ldm_x4(ah[mt], base + T_AHI + sw);
                ldm_x4(al[mt], base + T_ALO + sw);
            }
            #pragma unroll
            for (int p = 0; p < 2; p++) {
                uint32_t off = (uint32_t)((rowB + p * 16) * 128) + colB;
                uint32_t sw  = off ^ ((off >> 3) & 0x70);
                uint32_t t[4];
                ldm_x4(t, base + T_BHI + sw);
                bh[2*p][0] = t[0]; bh[2*p][1] = t[1];
                bh[2*p+1][0] = t[2]; bh[2*p+1][1] = t[3];
                ldm_x4(t, base + T_BLO + sw);
                bl[2*p][0] = t[0]; bl[2*p][1] = t[1];
                bl[2*p+1][0] = t[2]; bl[2*p+1][1] = t[3];
            }
            #pragma unroll
            for (int mt = 0; mt < 2; mt++)
                #pragma unroll
                for (int nt = 0; nt < 4; nt++) {
                    mma_bf16(acc[mt][nt], ah[mt], bh[nt]);
                    mma_bf16(acc[mt][nt], ah[mt], bl[nt]);
                    mma_bf16(acc[mt][nt], al[mt], bh[nt]);
                }
        }
    }

    #pragma unroll
    for (int mt = 0; mt < 2; mt++) {
        #pragma unroll
        for (int nt = 0; nt < 4; nt++) {
            int row = bm + wm * 32 + mt * 16 + (lane >> 2);
            int col = bn + wn * 32 + nt * 8 + (lane & 3) * 2;
            float* a = acc[mt][nt];
            float2 b2 = *(const float2*)(bias + col);
            float v0 = a[0] + b2.x, v1 = a[1] + b2.y;
            float v2 = a[2] + b2.x, v3 = a[3] + b2.y;
            if (mode == 0) {
                if (res) {
                    float2 r0 = *(const float2*)(res + (size_t)row * N + col);
                    float2 r1 = *(const float2*)(res + (size_t)(row + 8) * N + col);
                    v0 += r0.x; v1 += r0.y; v2 += r1.x; v3 += r1.y;
                }
                *(float2*)(C + (size_t)row * N + col)       = make_float2(v0, v1);
                *(float2*)(C + (size_t)(row + 8) * N + col) = make_float2(v2, v3);
            } else if (mode == 1) {
                v0 = 0.5f * v0 * (1.0f + erff(v0 * 0.7071067811865475f));
                v1 = 0.5f * v1 * (1.0f + erff(v1 * 0.7071067811865475f));
                v2 = 0.5f * v2 * (1.0f + erff(v2 * 0.7071067811865475f));
                v3 = 0.5f * v3 * (1.0f + erff(v3 * 0.7071067811865475f));
                uint32_t hi, lo;
                split2(v0, v1, hi, lo);
                *(uint32_t*)(Ohi + (size_t)row * N + col) = hi;
                *(uint32_t*)(Olo + (size_t)row * N + col) = lo;
                split2(v2, v3, hi, lo);
                *(uint32_t*)(Ohi + (size_t)(row + 8) * N + col) = hi;
                *(uint32_t*)(Olo + (size_t)(row + 8) * N + col) = lo;
            } else {
                store_qkv(row,     col, v0, v1, Ohi, Olo);
                store_qkv(row + 8, col, v2, v3, Ohi, Olo);
            }
        }
    }
}

// ---------------- HMMA flash attention ---------------------------------------
// grid (32 qtiles, 8 heads, 2 batch), 128 threads (4 warps, 16 q-rows each).
// smem: 2 KV stages x 32KB; Q tile ALIASED into stage 1.  64KB -> 3 CTAs/SM.
// ONE barrier per kt (wait(0) -> sync -> issue(next) -> compute).
#define AS_STAGE 0
#define AS_Q     32768              // = stage 1 base (aliased)
#define AS_QLO   (32768 + 8192)
#define ATTN_SMEM 65536

__global__ __launch_bounds__(128, 3)
void attn_tc(const __nv_bfloat16* __restrict__ qk_hi,
             const __nv_bfloat16* __restrict__ qk_lo,
             __nv_bfloat16* __restrict__ ohi, __nv_bfloat16* __restrict__ olo)
{
    extern __shared__ char smem[];
    uint32_t sb = smem_u32(smem);
    int qt = 31 - blockIdx.x;          // big tiles first (less tail)
    int hh = blockIdx.y, b = blockIdx.z;
    int tid = threadIdx.x, lane = tid & 31, warp = tid >> 5;
    int bh = b * 8 + hh;

    const __nv_bfloat16* qhi  = qk_hi;
    const __nv_bfloat16* qlo  = qk_lo;
    const __nv_bfloat16* khi  = qk_hi + QK_KOFF;
    const __nv_bfloat16* klo  = qk_lo + QK_KOFF;
    const __nv_bfloat16* vthi = qk_hi + QK_VOFF;
    const __nv_bfloat16* vtlo = qk_lo + QK_VOFF;

    #pragma unroll
    for (int i = 0; i < 4; i++) {
        int idx = tid + i * 128;
        int r = idx >> 3, c8 = idx & 7;
        uint32_t off = (uint32_t)(r * 128 + c8 * 16);
        uint32_t sw  = off ^ ((off >> 3) & 0x70);
        cp_async16(sb + AS_Q   + sw, qhi + ((size_t)bh * 2048 + qt * 64 + r) * 64 + c8 * 8);
        cp_async16(sb + AS_QLO + sw, qlo + ((size_t)bh * 2048 + qt * 64 + r) * 64 + c8 * 8);
    }
    asm volatile("cp.async.commit_group;" ::: "memory");

    auto load_kv = [&](int kt, int s) {
        uint32_t base = sb + AS_STAGE + s * 32768;
        #pragma unroll
        for (int i = 0; i < 4; i++) {
            int idx = tid + i * 128;
            int r = idx >> 3, c8 = idx & 7;
            uint32_t off = (uint32_t)(r * 128 + c8 * 16);
            uint32_t sw  = off ^ ((off >> 3) & 0x70);
            cp_async16(base + sw,         khi  + ((size_t)bh * 2048 + kt * 64 + r) * 64 + c8 * 8);
            cp_async16(base + 8192 + sw,  klo  + ((size_t)bh * 2048 + kt * 64 + r) * 64 + c8 * 8);
            cp_async16(base + 16384 + sw, vthi + ((size_t)bh * 64 + r) * 2048 + kt * 64 + c8 * 8);
            cp_async16(base + 24576 + sw, vtlo + ((size_t)bh * 64 + r) * 2048 + kt * 64 + c8 * 8);
        }
        asm volatile("cp.async.commit_group;" ::: "memory");
    };

    load_kv(0, 0);                      // stage 0 (does not touch Q alias)
    asm volatile("cp.async.wait_group 1;" ::: "memory");   // Q arrived
    __syncthreads();

    uint32_t Qh[4][4], Ql[4][4];
    {
        int rowA = warp * 16 + (lane & 15);
        #pragma unroll
        for (int kc = 0; kc < 4; kc++) {
            uint32_t colA = (uint32_t)(kc * 32 + ((lane >> 4) & 1) * 16);
            uint32_t off = (uint32_t)(rowA * 128) + colA;
            uint32_t sw  = off ^ ((off >> 3) & 0x70);
            ldm_x4(Qh[kc], sb + AS_Q   + sw);
            ldm_x4(Ql[kc], sb + AS_QLO + sw);
        }
    }
    __syncthreads();   // all warps done reading Q before stage 1 (alias) is written

    float O[8][4];
    #pragma unroll
    for (int i = 0; i < 8; i++)
        #pragma unroll
        for (int j = 0; j < 4; j++) O[i][j] = 0.0f;
    float m0 = -1e30f, m1 = -1e30f, l0 = 0.0f, l1 = 0.0f;

    int r0 = lane >> 2;
    int qrow0 = warp * 16 + r0, qrow1 = qrow0 + 8;

    for (int kt = 0; kt <= qt; kt++) {
        int s = kt & 1;
        asm volatile("cp.async.wait_group 0;" ::: "memory");
        __syncthreads();
        if (kt < qt) load_kv(kt + 1, s ^ 1);
        uint32_t base = sb + AS_STAGE + s * 32768;

        float S[8][4];
        #pragma unroll
        for (int i = 0; i < 8; i++)
            #pragma unroll
            for (int j = 0; j < 4; j++) S[i][j] = 0.0f;

        #pragma unroll
        for (int kc = 0; kc < 4; kc++) {
            #pragma unroll
            for (int sp = 0; sp < 4; sp++) {
                int rowB = sp * 16 + (lane & 7) + ((lane >> 4) << 3);
                uint32_t colB = (uint32_t)(kc * 32 + ((lane >> 3) & 1) * 16);
                uint32_t off = (uint32_t)(rowB * 128) + colB;
                uint32_t sw  = off ^ ((off >> 3) & 0x70);
                uint32_t kh[4], kl[4];
                ldm_x4(kh, base + sw);
                ldm_x4(kl, base + 8192 + sw);
                mma_bf16(S[2*sp],   Qh[kc], &kh[0]);
                mma_bf16(S[2*sp],   Qh[kc], &kl[0]);
                mma_bf16(S[2*sp],   Ql[kc], &kh[0]);
                mma_bf16(S[2*sp+1], Qh[kc], &kh[2]);
                mma_bf16(S[2*sp+1], Qh[kc], &kl[2]);
                mma_bf16(S[2*sp+1], Ql[kc], &kh[2]);
            }
        }

        bool diag = (kt == qt);
        float mx0 = -1e30f, mx1 = -1e30f;
        #pragma unroll
        for (int nt = 0; nt < 8; nt++) {
            int c0 = nt * 8 + (lane & 3) * 2;
            float v0 = S[nt][0] * 0.125f, v1 = S[nt][1] * 0.125f;
            float v2 = S[nt][2] * 0.125f, v3 = S[nt][3] * 0.125f;
            if (diag) {
                if (c0     > qrow0) v0 = -1e30f;
                if (c0 + 1 > qrow0) v1 = -1e30f;
                if (c0     > qrow1) v2 = -1e30f;
                if (c0 + 1 > qrow1) v3 = -1e30f;
            }
            S[nt][0] = v0; S[nt][1] = v1; S[nt][2] = v2; S[nt][3] = v3;
            mx0 = fmaxf(mx0, fmaxf(v0, v1));
            mx1 = fmaxf(mx1, fmaxf(v2, v3));
        }
        mx0 = fmaxf(mx0, __shfl_xor_sync(0xffffffffu, mx0, 1));
        mx0 = fmaxf(mx0, __shfl_xor_sync(0xffffffffu, mx0, 2));
        mx1 = fmaxf(mx1, __shfl_xor_sync(0xffffffffu, mx1, 1));
        mx1 = fmaxf(mx1, __shfl_xor_sync(0xffffffffu, mx1, 2));

        float mn0 = fmaxf(m0, mx0), mn1 = fmaxf(m1, mx1);
        float corr0 = __expf(m0 - mn0), corr1 = __expf(m1 - mn1);
        m0 = mn0; m1 = mn1;

        uint32_t Ph[4][4], Pl[4][4];
        float ls0 = 0.0f, ls1 = 0.0f;
        #pragma unroll
        for (int kcs = 0; kcs < 4; kcs++) {
            float p00 = __expf(S[2*kcs][0]   - mn0), p01 = __expf(S[2*kcs][1]   - mn0);
            float p02 = __expf(S[2*kcs][2]   - mn1), p03 = __expf(S[2*kcs][3]   - mn1);
            float p10 = __expf(S[2*kcs+1][0] - mn0), p11 = __expf(S[2*kcs+1][1] - mn0);
            float p12 = __expf(S[2*kcs+1][2] - mn1), p13 = __expf(S[2*kcs+1][3] - mn1);
            ls0 += p00 + p01 + p10 + p11;
            ls1 += p02 + p03 + p12 + p13;
            split2(p00, p01, Ph[kcs][0], Pl[kcs][0]);
            split2(p02, p03, Ph[kcs][1], Pl[kcs][1]);
            split2(p10, p11, Ph[kcs][2], Pl[kcs][2]);
            split2(p12, p13, Ph[kcs][3], Pl[kcs][3]);
        }
        ls0 += __shfl_xor_sync(0xffffffffu, ls0, 1);
        ls0 += __shfl_xor_sync(0xffffffffu, ls0, 2);
        ls1 += __shfl_xor_sync(0xffffffffu, ls1, 1);
        ls1 += __shfl_xor_sync(0xffffffffu, ls1, 2);
        l0 = l0 * corr0 + ls0;
        l1 = l1 * corr1 + ls1;

        #pragma unroll
        for (int dt = 0; dt < 8; dt++) {
            O[dt][0] *= corr0; O[dt][1] *= corr0;
            O[dt][2] *= corr1; O[dt][3] *= corr1;
        }

        #pragma unroll
        for (int kcs = 0; kcs < 4; kcs++) {
            #pragma unroll
            for (int dp = 0; dp < 4; dp++) {
                int rowB = dp * 16 + (lane & 7) + ((lane >> 4) << 3);
                uint32_t colB = (uint32_t)(kcs * 32 + ((lane >> 3) & 1) * 16);
                uint32_t off = (uint32_t)(rowB * 128) + colB;
                uint32_t sw  = off ^ ((off >> 3) & 0x70);
                uint32_t vh[4], vl[4];
                ldm_x4(vh, base + 16384 + sw);
                ldm_x4(vl, base + 24576 + sw);
                mma_bf16(O[2*dp],   Ph[kcs], &vh[0]);
                mma_bf16(O[2*dp],   Ph[kcs], &vl[0]);
                mma_bf16(O[2*dp],   Pl[kcs], &vh[0]);
                mma_bf16(O[2*dp+1], Ph[kcs], &vh[2]);
                mma_bf16(O[2*dp+1], Ph[kcs], &vl[2]);
                mma_bf16(O[2*dp+1], Pl[kcs], &vh[2]);
            }
        }
    }

    float il0 = 1.0f / l0, il1 = 1.0f / l1;
    int grow0 = b * 2048 + qt * 64 + qrow0;
    int grow1 = grow0 + 8;
    #pragma unroll
    for (int dt = 0; dt < 8; dt++) {
        int d = dt * 8 + (lane & 3) * 2;
        uint32_t hi, lo;
        split2(O[dt][0] * il0, O[dt][1] * il0, hi, lo);
        *(uint32_t*)(ohi + (size_t)grow0 * 512 + hh * 64 + d) = hi;
        *(uint32_t*)(olo + (size_t)grow0 * 512 + hh * 64 + d) = lo;
        split2(O[dt][2] * il1, O[dt][3] * il1, hi, lo);
        *(uint32_t*)(ohi + (size_t)grow1 * 512 + hh * 64 + d) = hi;
        *(uint32_t*)(olo + (size_t)grow1 * 512 + hh * 64 + d) = lo;
    }
}

// ---------------- launch orchestration ---------------------------------------
extern "C" void kernel_launch(void* const* d_in, const int* in_sizes, int n_in,
                              void* d_out, int out_size)
{
    const int*   x      = (const int*)  d_in[0];
    const float* emb    = (const float*)d_in[1];
    const float* ln1_s  = (const float*)d_in[2];
    const float* ln1_b  = (const float*)d_in[3];
    const float* qkv_w  = (const float*)d_in[4];
    const float* qkv_b  = (const float*)d_in[5];
    const float* afc_w  = (const float*)d_in[6];
    const float* afc_b  = (const float*)d_in[7];
    const float* ln2_s  = (const float*)d_in[8];
    const float* ln2_b  = (const float*)d_in[9];
    const float* ff_w1  = (const float*)d_in[10];
    const float* ff_b1  = (const float*)d_in[11];
    const float* ff_w2  = (const float*)d_in[12];
    const float* ff_b2  = (const float*)d_in[13];
    const float* lnf_s  = (const float*)d_in[14];
    const float* lnf_b  = (const float*)d_in[15];
    const float* fc_w   = (const float*)d_in[16];
    const float* fc_b   = (const float*)d_in[17];
    float* out = (float*)d_out;

    float *h;
    __nv_bfloat16 *ahi, *alo, *fhi, *flo, *qkhi, *qklo, *whi, *wlo;
    cudaGetSymbolAddress((void**)&h,    g_h);
    cudaGetSymbolAddress((void**)&ahi,  g_ahi);
    cudaGetSymbolAddress((void**)&alo,  g_alo);
    cudaGetSymbolAddress((void**)&fhi,  g_fhi);
    cudaGetSymbolAddress((void**)&flo,  g_flo);
    cudaGetSymbolAddress((void**)&qkhi, g_qkhi);
    cudaGetSymbolAddress((void**)&qklo, g_qklo);
    cudaGetSymbolAddress((void**)&whi,  g_whi);
    cudaGetSymbolAddress((void**)&wlo,  g_wlo);

    cudaFuncSetAttribute(gemm_tc, cudaFuncAttributeMaxDynamicSharedMemorySize, GEMM_SMEM);
    cudaFuncSetAttribute(attn_tc, cudaFuncAttributeMaxDynamicSharedMemorySize, ATTN_SMEM);

    // ---- weight prep: batched over layers, 5 launches total ----
    wprep_kernel<<<dim3(1536/64, 512/64, NLAYER), 256>>>(
        qkv_w, whi + W_OFF_QKV, wlo + W_OFF_QKV, 512, 1536,
        (size_t)512*1536, (size_t)W_LSTRIDE);
    wprep_kernel<<<dim3(512/64, 512/64, NLAYER), 256>>>(
        afc_w, whi + W_OFF_AFC, wlo + W_OFF_AFC, 512, 512,
        (size_t)512*512, (size_t)W_LSTRIDE);
    wprep_kernel<<<dim3(2048/64, 512/64, NLAYER), 256>>>(
        ff_w1, whi + W_OFF_FF1, wlo + W_OFF_FF1, 512, 2048,
        (size_t)512*2048, (size_t)W_LSTRIDE);
    wprep_kernel<<<dim3(512/64, 2048/64, NLAYER), 256>>>(
        ff_w2, whi + W_OFF_FF2, wlo + W_OFF_FF2, 2048, 512,
        (size_t)2048*512, (size_t)W_LSTRIDE);
    wprep_kernel<<<dim3(32000/64, 512/64, 1), 256>>>(
        fc_w, whi + W_OFF_FC, wlo + W_OFF_FC, 512, 32000, 0, 0);

    embed_kernel<<<M_ROWS, 256>>>(x, emb, h);

    for (int l = 0; l < NLAYER; l++) {
        ln_split_kernel<<<M_ROWS, 128>>>(h, ln1_s + l*D_MODEL, ln1_b + l*D_MODEL, ahi, alo);
        // qkv (scatter mode)
        gemm_tc<<<dim3(32, 24), 256, GEMM_SMEM>>>(
            ahi, alo, whi + l*W_LSTRIDE + W_OFF_QKV, wlo + l*W_LSTRIDE + W_OFF_QKV,
            qkv_b + (size_t)l*1536, nullptr, nullptr, qkhi, qklo, M_ROWS, 1536, 512, 2);
        // attention -> ahi/alo
        attn_tc<<<dim3(32, NHEAD, BATCH), 128, ATTN_SMEM>>>(qkhi, qklo, ahi, alo);
        // h = h + att @ afc_w + afc_b
        gemm_tc<<<dim3(32, 8), 256, GEMM_SMEM>>>(
            ahi, alo, whi + l*W_LSTRIDE + W_OFF_AFC, wlo + l*W_LSTRIDE + W_OFF_AFC,
            afc_b + (size_t)l*512, h, h, nullptr, nullptr, M_ROWS, 512, 512, 0);
        ln_split_kernel<<<M_ROWS, 128>>>(h, ln2_s + l*D_MODEL, ln2_b + l*D_MODEL, ahi, alo);
        // ff = gelu(...) -> fhi/flo (split mode)
        gemm_tc<<<dim3(32, 32), 256, GEMM_SMEM>>>(
            ahi, alo, whi + l*W_LSTRIDE + W_OFF_FF1, wlo + l*W_LSTRIDE + W_OFF_FF1,
            ff_b1 + (size_t)l*2048, nullptr, nullptr, fhi, flo, M_ROWS, 2048, 512, 1);
        // h = h + ff @ ff_w2 + ff_b2
        gemm_tc<<<dim3(32, 8), 256, GEMM_SMEM>>>(
            fhi, flo, whi + l*W_LSTRIDE + W_OFF_FF2, wlo + l*W_LSTRIDE + W_OFF_FF2,
            ff_b2 + (size_t)l*512, h, h, nullptr, nullptr, M_ROWS, 512, 2048, 0);
    }

    ln_split_kernel<<<M_ROWS, 128>>>(h, lnf_s, lnf_b, ahi, alo);
    gemm_tc<<<dim3(32, 500), 256, GEMM_SMEM>>>(
        ahi, alo, whi + W_OFF_FC, wlo + W_OFF_FC,
        fc_b, nullptr, out, nullptr, nullptr, M_ROWS, VOCAB, 512, 0);
}

// round 15
// speedup vs baseline: 1.0200x; 1.0200x over previous
#include <cuda_runtime.h>
#include <cuda_bf16.h>
#include <cstdint>
#include <stdint.h>
#include <math.h>

#define D_MODEL 512
#define NHEAD   8
#define DHEAD   64
#define NLAYER  8
#define FF_DIM  2048
#define VOCAB   32000
#define BATCH   2
#define SEQ     2048
#define M_ROWS  (BATCH*SEQ)   // 4096

// ---------------- scratch (static __device__ globals; no allocs allowed) ----
__device__ float g_h[M_ROWS * D_MODEL];                  // residual stream fp32

__device__ __nv_bfloat16 g_ahi[M_ROWS * D_MODEL];        // ln out / attn out
__device__ __nv_bfloat16 g_alo[M_ROWS * D_MODEL];
__device__ __nv_bfloat16 g_fhi[M_ROWS * FF_DIM];         // ff1 out
__device__ __nv_bfloat16 g_flo[M_ROWS * FF_DIM];

// q/k/vt packed: Q[BH,T,DH] @0, K[BH,T,DH] @2097152, Vt[BH,DH,T] @4194304
#define QK_KOFF 2097152
#define QK_VOFF 4194304
__device__ __nv_bfloat16 g_qkhi[6291456];
__device__ __nv_bfloat16 g_qklo[6291456];

// transposed weights, bf16 hi/lo.
#define W_LSTRIDE 3145728ULL
#define W_OFF_QKV 0ULL
#define W_OFF_AFC 786432ULL
#define W_OFF_FF1 1048576ULL
#define W_OFF_FF2 2097152ULL
#define W_OFF_FC  (8ULL * W_LSTRIDE)
#define W_TOTAL   (W_OFF_FC + 32000ULL * 512ULL)
__device__ __nv_bfloat16 g_whi[W_TOTAL];
__device__ __nv_bfloat16 g_wlo[W_TOTAL];

// PDL entry sync: wait for upstream grid's writes before reading anything.
__device__ __forceinline__ void pdl_wait() {
#if defined(__CUDA_ARCH__) && (__CUDA_ARCH__ >= 900)
    cudaGridDependencySynchronize();
#endif
}

// ---------------- PTX helpers (sm_80-compatible only) ------------------------
__device__ __forceinline__ uint32_t smem_u32(const void* p) {
    uint32_t a;
    asm("{ .reg .u64 t; cvta.to.shared.u64 t, %1; cvt.u32.u64 %0, t; }"
        : "=r"(a) : "l"(p));
    return a;
}

__device__ __forceinline__ void cp_async16(uint32_t saddr, const void* gaddr) {
    asm volatile("cp.async.cg.shared.global [%0], [%1], 16;"
                 :: "r"(saddr), "l"(gaddr));
}

__device__ __forceinline__ void ldm_x4(uint32_t* r, uint32_t addr) {
    asm volatile("ldmatrix.sync.aligned.m8n8.x4.shared.b16 {%0,%1,%2,%3}, [%4];"
                 : "=r"(r[0]), "=r"(r[1]), "=r"(r[2]), "=r"(r[3]) : "r"(addr));
}

__device__ __forceinline__ void mma_bf16(float* c, const uint32_t* a, const uint32_t* b) {
    asm volatile(
        "mma.sync.aligned.m16n8k16.row.col.f32.bf16.bf16.f32 "
        "{%0,%1,%2,%3}, {%4,%5,%6,%7}, {%8,%9}, {%0,%1,%2,%3};"
        : "+f"(c[0]), "+f"(c[1]), "+f"(c[2]), "+f"(c[3])
        : "r"(a[0]), "r"(a[1]), "r"(a[2]), "r"(a[3]), "r"(b[0]), "r"(b[1]));
}

// pack two floats into bf16x2 hi reg + residual lo reg
__device__ __forceinline__ void split2(float x, float y, uint32_t& hi, uint32_t& lo) {
    __nv_bfloat16 hx = __float2bfloat16(x), hy = __float2bfloat16(y);
    __nv_bfloat162 H{hx, hy};
    __nv_bfloat162 L{__float2bfloat16(x - __bfloat162float(hx)),
                     __float2bfloat16(y - __bfloat162float(hy))};
    hi = *reinterpret_cast<uint32_t*>(&H);
    lo = *reinterpret_cast<uint32_t*>(&L);
}

// ---------------- embedding + positional encoding ---------------------------
__global__ void embed_kernel(const int* __restrict__ x,
                             const float* __restrict__ emb,
                             float* __restrict__ h)
{
    pdl_wait();
    int row = blockIdx.x;
    int t   = row % SEQ;
    int tok = x[row];
    int i   = threadIdx.x;
    float f = expf((float)(2 * i) * (-9.210340371976184f / 512.0f));
    float ang = (float)t * f;
    float s, c;
    sincosf(ang, &s, &c);
    const float* e = emb + (size_t)tok * D_MODEL;
    float* hp = h + (size_t)row * D_MODEL;
    hp[2 * i]     = e[2 * i]     + s;
    hp[2 * i + 1] = e[2 * i + 1] + c;
}

// ---------------- layernorm -> bf16 hi/lo split ------------------------------
__global__ void ln_split_kernel(const float* __restrict__ x,
                                const float* __restrict__ scale,
                                const float* __restrict__ bias,
                                __nv_bfloat16* __restrict__ yhi,
                                __nv_bfloat16* __restrict__ ylo)
{
    pdl_wait();
    int row = blockIdx.x;
    int tid = threadIdx.x;
    const float4* xr = (const float4*)(x + (size_t)row * D_MODEL);
    float4 v = xr[tid];
    float s  = v.x + v.y + v.z + v.w;
    float sq = v.x*v.x + v.y*v.y + v.z*v.z + v.w*v.w;
    #pragma unroll
    for (int o = 16; o > 0; o >>= 1) {
        s  += __shfl_xor_sync(0xffffffffu, s,  o);
        sq += __shfl_xor_sync(0xffffffffu, sq, o);
    }
    __shared__ float ss[4], ssq[4];
    int wid = tid >> 5, lane = tid & 31;
    if (lane == 0) { ss[wid] = s; ssq[wid] = sq; }
    __syncthreads();
    s  = ss[0]  + ss[1]  + ss[2]  + ss[3];
    sq = ssq[0] + ssq[1] + ssq[2] + ssq[3];
    float mu  = s * (1.0f / D_MODEL);
    float var = sq * (1.0f / D_MODEL) - mu * mu;
    float inv = rsqrtf(var + 1e-5f);
    float4 sc = ((const float4*)scale)[tid];
    float4 bi = ((const float4*)bias)[tid];
    float o0 = (v.x - mu) * inv * sc.x + bi.x;
    float o1 = (v.y - mu) * inv * sc.y + bi.y;
    float o2 = (v.z - mu) * inv * sc.z + bi.z;
    float o3 = (v.w - mu) * inv * sc.w + bi.w;
    uint32_t h0, l0, h1, l1;
    split2(o0, o1, h0, l0);
    split2(o2, o3, h1, l1);
    uint32_t* ph = (uint32_t*)(yhi + (size_t)row * D_MODEL);
    uint32_t* pl = (uint32_t*)(ylo + (size_t)row * D_MODEL);
    ph[tid*2] = h0; ph[tid*2+1] = h1;
    pl[tid*2] = l0; pl[tid*2+1] = l1;
}

// ---------------- weight transpose + split (batched over layers) -------------
// W[K,N] (fp32) -> Wt hi/lo [N,K] bf16.  64x64 tiles, 256 threads.
__global__ __launch_bounds__(256)
void wprep_kernel(const float* __restrict__ W,
                  __nv_bfloat16* __restrict__ hi,
                  __nv_bfloat16* __restrict__ lo,
                  int K, int N, size_t wstride, size_t ostride)
{
    pdl_wait();
    __shared__ float t[64][65];
    const float* Wl = W + (size_t)blockIdx.z * wstride;
    int n0 = blockIdx.x * 64, k0 = blockIdx.y * 64;
    int tid = threadIdx.x;
    #pragma unroll
    for (int j = 0; j < 4; j++) {
        int idx = tid + j * 256;
        int kk = idx >> 4;
        int c4 = idx & 15;
        float4 v = *(const float4*)&Wl[(size_t)(k0 + kk) * N + n0 + c4 * 4];
        t[kk][c4*4+0] = v.x; t[kk][c4*4+1] = v.y;
        t[kk][c4*4+2] = v.z; t[kk][c4*4+3] = v.w;
    }
    __syncthreads();
    int tx = tid & 31, ty = tid >> 5;
    size_t obase = (size_t)blockIdx.z * ostride;
    #pragma unroll
    for (int j = 0; j < 8; j++) {
        int nl = ty + j * 8;
        float v0 = t[tx*2][nl], v1 = t[tx*2+1][nl];
        uint32_t h2, l2;
        split2(v0, v1, h2, l2);
        size_t o = obase + (size_t)(n0 + nl) * K + k0 + tx * 2;
        *(uint32_t*)(hi + o) = h2;
        *(uint32_t*)(lo + o) = l2;
    }
}

// ---------------- HMMA bf16x3 GEMM (256 thr, 8 warps 4x2, BM128xBN64) --------
// 2 CTAs/SM (96KB smem), 2-stage cp.async pipeline (R13 ordering:
// issue(next) BEFORE wait(1) so next loads fly during the wait).
// mode 0: C fp32 = [res +] A@W + bias
// mode 1: Ohi/Olo bf16 = split(gelu(A@W + bias))
// mode 2: scatter q/k/vt hi/lo from A@W + bias
#define CHUNK_K 64
#define STAGE_BYTES 49152
#define T_AHI 0
#define T_ALO 16384
#define T_BHI 32768
#define T_BLO 40960
#define GEMM_SMEM (2*STAGE_BYTES)

__device__ __forceinline__ void store_qkv(int row, int col, float v0, float v1,
                                          __nv_bfloat16* Ohi, __nv_bfloat16* Olo)
{
    int sect = col >> 9;
    int hh = (col >> 6) & 7;
    int d = col & 63;
    int bb = row >> 11, tt = row & 2047;
    int bh = bb * 8 + hh;
    uint32_t hi, lo;
    split2(v0, v1, hi, lo);
    if (sect < 2) {
        size_t off = (size_t)sect * QK_KOFF + ((size_t)bh * 2048 + tt) * 64 + d;
        *(uint32_t*)(Ohi + off) = hi;
        *(uint32_t*)(Olo + off) = lo;
    } else {
        size_t off = QK_VOFF + ((size_t)bh * 64 + d) * 2048 + tt;
        __nv_bfloat162 H = *reinterpret_cast<__nv_bfloat162*>(&hi);
        __nv_bfloat162 L = *reinterpret_cast<__nv_bfloat162*>(&lo);
        Ohi[off] = H.x; Ohi[off + 2048] = H.y;
        Olo[off] = L.x; Olo[off + 2048] = L.y;
    }
}

__global__ __launch_bounds__(256, 2)
void gemm_tc(const __nv_bfloat16* __restrict__ Ahi, const __nv_bfloat16* __restrict__ Alo,
             const __nv_bfloat16* __restrict__ Bhi, const __nv_bfloat16* __restrict__ Blo,
             const float* __restrict__ bias, const float* __restrict__ res,
             float* __restrict__ C, __nv_bfloat16* __restrict__ Ohi,
             __nv_bfloat16* __restrict__ Olo, int M, int N, int K, int mode)
{
    pdl_wait();
    extern __shared__ char smem[];
    uint32_t sb = smem_u32(smem);
    int tid = threadIdx.x, lane = tid & 31, wid = tid >> 5;
    int bm = blockIdx.x * 128, bn = blockIdx.y * 64;   // bm fast: L2 B-tile reuse
    int wm = wid >> 1, wn = wid & 1;       // 4 x 2 warp grid, warp tile 32x32

    float acc[2][4][4];
    #pragma unroll
    for (int i = 0; i < 2; i++)
        #pragma unroll
        for (int j = 0; j < 4; j++)
            #pragma unroll
            for (int k = 0; k < 4; k++) acc[i][j][k] = 0.0f;

    int nch = K / CHUNK_K;

    auto issue = [&](int c, int s) {
        uint32_t base = sb + s * STAGE_BYTES;
        int k0 = c * CHUNK_K;
        #pragma unroll
        for (int i = 0; i < 4; i++) {
            int idx = tid + i * 256;
            int r = idx >> 3, q = idx & 7;
            uint32_t off = (uint32_t)(r * 128 + q * 16);
            uint32_t sw  = off ^ ((off >> 3) & 0x70);
            cp_async16(base + T_AHI + sw, Ahi + (size_t)(bm + r) * K + k0 + q * 8);
            cp_async16(base + T_ALO + sw, Alo + (size_t)(bm + r) * K + k0 + q * 8);
        }
        #pragma unroll
        for (int i = 0; i < 2; i++) {
            int idx = tid + i * 256;
            int r = idx >> 3, q = idx & 7;
            uint32_t off = (uint32_t)(r * 128 + q * 16);
            uint32_t sw  = off ^ ((off >> 3) & 0x70);
            cp_async16(base + T_BHI + sw, Bhi + (size_t)(bn + r) * K + k0 + q * 8);
            cp_async16(base + T_BLO + sw, Blo + (size_t)(bn + r) * K + k0 + q * 8);
        }
        asm volatile("cp.async.commit_group;" ::: "memory");
    };

    issue(0, 0);
    for (int c = 0; c < nch; c++) {
        int s = c & 1;
        if (c + 1 < nch) {
            issue(c + 1, s ^ 1);
            asm volatile("cp.async.wait_group 1;" ::: "memory");
        } else {
            asm volatile("cp.async.wait_group 0;" ::: "memory");
        }
        __syncthreads();

        uint32_t base = sb + s * STAGE_BYTES;
        int rowA  = wm * 32 + (lane & 15);
        int rowB  = wn * 32 + (lane & 7) + ((lane >> 4) << 3);
        #pragma unroll
        for (int ks = 0; ks < 4; ks++) {
            uint32_t ah[2][4], al[2][4], bh[4][2], bl[4][2];
            uint32_t colA = (uint32_t)(ks * 32 + ((lane >> 4) & 1) * 16);
            uint32_t colB = (uint32_t)(ks * 32 + ((lane >> 3) & 1) * 16);
            #pragma unroll
            for (int mt = 0; mt < 2; mt++) {
                uint32_t off = (uint32_t)((rowA + mt * 16) * 128) + colA;
                uint32_t sw  = off ^ ((off >> 3) & 0x70);
                ldm_x4(ah[mt], base + T_AHI + sw);
                ldm_x4(al[mt], base + T_ALO + sw);
            }
            #pragma unroll
            for (int p = 0; p < 2; p++) {
                uint32_t off = (uint32_t)((rowB + p * 16) * 128) + colB;
                uint32_t sw  = off ^ ((off >> 3) & 0x70);
                uint32_t t[4];
                ldm_x4(t, base + T_BHI + sw);
                bh[2*p][0] = t[0]; bh[2*p][1] = t[1];
                bh[2*p+1][0] = t[2]; bh[2*p+1][1] = t[3];
                ldm_x4(t, base + T_BLO + sw);
                bl[2*p][0] = t[0]; bl[2*p][1] = t[1];
                bl[2*p+1][0] = t[2]; bl[2*p+1][1] = t[3];
            }
            #pragma unroll
            for (int mt = 0; mt < 2; mt++)
                #pragma unroll
                for (int nt = 0; nt < 4; nt++) {
                    mma_bf16(acc[mt][nt], ah[mt], bh[nt]);
                    mma_bf16(acc[mt][nt], ah[mt], bl[nt]);
                    mma_bf16(acc[mt][nt], al[mt], bh[nt]);
                }
        }
        __syncthreads();
    }

    #pragma unroll
    for (int mt = 0; mt < 2; mt++) {
        #pragma unroll
        for (int nt = 0; nt < 4; nt++) {
            int row = bm + wm * 32 + mt * 16 + (lane >> 2);
            int col = bn + wn * 32 + nt * 8 + (lane & 3) * 2;
            float* a = acc[mt][nt];
            float2 b2 = *(const float2*)(bias + col);
            float v0 = a[0] + b2.x, v1 = a[1] + b2.y;
            float v2 = a[2] + b2.x, v3 = a[3] + b2.y;
            if (mode == 0) {
                if (res) {
                    float2 r0 = *(const float2*)(res + (size_t)row * N + col);
                    float2 r1 = *(const float2*)(res + (size_t)(row + 8) * N + col);
                    v0 += r0.x; v1 += r0.y; v2 += r1.x; v3 += r1.y;
                }
                *(float2*)(C + (size_t)row * N + col)       = make_float2(v0, v1);
                *(float2*)(C + (size_t)(row + 8) * N + col) = make_float2(v2, v3);
            } else if (mode == 1) {
                v0 = 0.5f * v0 * (1.0f + erff(v0 * 0.7071067811865475f));
                v1 = 0.5f * v1 * (1.0f + erff(v1 * 0.7071067811865475f));
                v2 = 0.5f * v2 * (1.0f + erff(v2 * 0.7071067811865475f));
                v3 = 0.5f * v3 * (1.0f + erff(v3 * 0.7071067811865475f));
                uint32_t hi, lo;
                split2(v0, v1, hi, lo);
                *(uint32_t*)(Ohi + (size_t)row * N + col) = hi;
                *(uint32_t*)(Olo + (size_t)row * N + col) = lo;
                split2(v2, v3, hi, lo);
                *(uint32_t*)(Ohi + (size_t)(row + 8) * N + col) = hi;
                *(uint32_t*)(Olo + (size_t)(row + 8) * N + col) = lo;
            } else {
                store_qkv(row,     col, v0, v1, Ohi, Olo);
                store_qkv(row + 8, col, v2, v3, Ohi, Olo);
            }
        }
    }
}

// ---------------- HMMA flash attention ---------------------------------------
// grid (32 qtiles, 8 heads, 2 batch), 128 threads (4 warps, 16 q-rows each).
// smem: 2 KV stages x 32KB; Q tile ALIASED into stage 1.  64KB -> 3 CTAs/SM.
// R13 pipeline ordering (issue-then-wait).
#define AS_STAGE 0
#define AS_Q     32768              // = stage 1 base (aliased)
#define AS_QLO   (32768 + 8192)
#define ATTN_SMEM 65536

__global__ __launch_bounds__(128, 3)
void attn_tc(const __nv_bfloat16* __restrict__ qk_hi,
             const __nv_bfloat16* __restrict__ qk_lo,
             __nv_bfloat16* __restrict__ ohi, __nv_bfloat16* __restrict__ olo)
{
    pdl_wait();
    extern __shared__ char smem[];
    uint32_t sb = smem_u32(smem);
    int qt = 31 - blockIdx.x;          // big tiles first (less tail)
    int hh = blockIdx.y, b = blockIdx.z;
    int tid = threadIdx.x, lane = tid & 31, warp = tid >> 5;
    int bh = b * 8 + hh;

    const __nv_bfloat16* qhi  = qk_hi;
    const __nv_bfloat16* qlo  = qk_lo;
    const __nv_bfloat16* khi  = qk_hi + QK_KOFF;
    const __nv_bfloat16* klo  = qk_lo + QK_KOFF;
    const __nv_bfloat16* vthi = qk_hi + QK_VOFF;
    const __nv_bfloat16* vtlo = qk_lo + QK_VOFF;

    #pragma unroll
    for (int i = 0; i < 4; i++) {
        int idx = tid + i * 128;
        int r = idx >> 3, c8 = idx & 7;
        uint32_t off = (uint32_t)(r * 128 + c8 * 16);
        uint32_t sw  = off ^ ((off >> 3) & 0x70);
        cp_async16(sb + AS_Q   + sw, qhi + ((size_t)bh * 2048 + qt * 64 + r) * 64 + c8 * 8);
        cp_async16(sb + AS_QLO + sw, qlo + ((size_t)bh * 2048 + qt * 64 + r) * 64 + c8 * 8);
    }
    asm volatile("cp.async.commit_group;" ::: "memory");

    auto load_kv = [&](int kt, int s) {
        uint32_t base = sb + AS_STAGE + s * 32768;
        #pragma unroll
        for (int i = 0; i < 4; i++) {
            int idx = tid + i * 128;
            int r = idx >> 3, c8 = idx & 7;
            uint32_t off = (uint32_t)(r * 128 + c8 * 16);
            uint32_t sw  = off ^ ((off >> 3) & 0x70);
            cp_async16(base + sw,         khi  + ((size_t)bh * 2048 + kt * 64 + r) * 64 + c8 * 8);
            cp_async16(base + 8192 + sw,  klo  + ((size_t)bh * 2048 + kt * 64 + r) * 64 + c8 * 8);
            cp_async16(base + 16384 + sw, vthi + ((size_t)bh * 64 + r) * 2048 + kt * 64 + c8 * 8);
            cp_async16(base + 24576 + sw, vtlo + ((size_t)bh * 64 + r) * 2048 + kt * 64 + c8 * 8);
        }
        asm volatile("cp.async.commit_group;" ::: "memory");
    };

    load_kv(0, 0);                      // stage 0 (does not touch Q alias)
    asm volatile("cp.async.wait_group 1;" ::: "memory");   // Q arrived
    __syncthreads();

    uint32_t Qh[4][4], Ql[4][4];
    {
        int rowA = warp * 16 + (lane & 15);
        #pragma unroll
        for (int kc = 0; kc < 4; kc++) {
            uint32_t colA = (uint32_t)(kc * 32 + ((lane >> 4) & 1) * 16);
            uint32_t off = (uint32_t)(rowA * 128) + colA;
            uint32_t sw  = off ^ ((off >> 3) & 0x70);
            ldm_x4(Qh[kc], sb + AS_Q   + sw);
            ldm_x4(Ql[kc], sb + AS_QLO + sw);
        }
    }
    __syncthreads();   // all warps done reading Q before stage 1 (alias) is written

    float O[8][4];
    #pragma unroll
    for (int i = 0; i < 8; i++)
        #pragma unroll
        for (int j = 0; j < 4; j++) O[i][j] = 0.0f;
    float m0 = -1e30f, m1 = -1e30f, l0 = 0.0f, l1 = 0.0f;

    int r0 = lane >> 2;
    int qrow0 = warp * 16 + r0, qrow1 = qrow0 + 8;

    for (int kt = 0; kt <= qt; kt++) {
        int s = kt & 1;
        if (kt < qt) {
            load_kv(kt + 1, s ^ 1);
            asm volatile("cp.async.wait_group 1;" ::: "memory");
        } else {
            asm volatile("cp.async.wait_group 0;" ::: "memory");
        }
        __syncthreads();
        uint32_t base = sb + AS_STAGE + s * 32768;

        float S[8][4];
        #pragma unroll
        for (int i = 0; i < 8; i++)
            #pragma unroll
            for (int j = 0; j < 4; j++) S[i][j] = 0.0f;

        #pragma unroll
        for (int kc = 0; kc < 4; kc++) {
            #pragma unroll
            for (int sp = 0; sp < 4; sp++) {
                int rowB = sp * 16 + (lane & 7) + ((lane >> 4) << 3);
                uint32_t colB = (uint32_t)(kc * 32 + ((lane >> 3) & 1) * 16);
                uint32_t off = (uint32_t)(rowB * 128) + colB;
                uint32_t sw  = off ^ ((off >> 3) & 0x70);
                uint32_t kh[4], kl[4];
                ldm_x4(kh, base + sw);
                ldm_x4(kl, base + 8192 + sw);
                mma_bf16(S[2*sp],   Qh[kc], &kh[0]);
                mma_bf16(S[2*sp],   Qh[kc], &kl[0]);
                mma_bf16(S[2*sp],   Ql[kc], &kh[0]);
                mma_bf16(S[2*sp+1], Qh[kc], &kh[2]);
                mma_bf16(S[2*sp+1], Qh[kc], &kl[2]);
                mma_bf16(S[2*sp+1], Ql[kc], &kh[2]);
            }
        }

        bool diag = (kt == qt);
        float mx0 = -1e30f, mx1 = -1e30f;
        #pragma unroll
        for (int nt = 0; nt < 8; nt++) {
            int c0 = nt * 8 + (lane & 3) * 2;
            float v0 = S[nt][0] * 0.125f, v1 = S[nt][1] * 0.125f;
            float v2 = S[nt][2] * 0.125f, v3 = S[nt][3] * 0.125f;
            if (diag) {
                if (c0     > qrow0) v0 = -1e30f;
                if (c0 + 1 > qrow0) v1 = -1e30f;
                if (c0     > qrow1) v2 = -1e30f;
                if (c0 + 1 > qrow1) v3 = -1e30f;
            }
            S[nt][0] = v0; S[nt][1] = v1; S[nt][2] = v2; S[nt][3] = v3;
            mx0 = fmaxf(mx0, fmaxf(v0, v1));
            mx1 = fmaxf(mx1, fmaxf(v2, v3));
        }
        mx0 = fmaxf(mx0, __shfl_xor_sync(0xffffffffu, mx0, 1));
        mx0 = fmaxf(mx0, __shfl_xor_sync(0xffffffffu, mx0, 2));
        mx1 = fmaxf(mx1, __shfl_xor_sync(0xffffffffu, mx1, 1));
        mx1 = fmaxf(mx1, __shfl_xor_sync(0xffffffffu, mx1, 2));

        float mn0 = fmaxf(m0, mx0), mn1 = fmaxf(m1, mx1);
        float corr0 = __expf(m0 - mn0), corr1 = __expf(m1 - mn1);
        m0 = mn0; m1 = mn1;

        uint32_t Ph[4][4], Pl[4][4];
        float ls0 = 0.0f, ls1 = 0.0f;
        #pragma unroll
        for (int kcs = 0; kcs < 4; kcs++) {
            float p00 = __expf(S[2*kcs][0]   - mn0), p01 = __expf(S[2*kcs][1]   - mn0);
            float p02 = __expf(S[2*kcs][2]   - mn1), p03 = __expf(S[2*kcs][3]   - mn1);
            float p10 = __expf(S[2*kcs+1][0] - mn0), p11 = __expf(S[2*kcs+1][1] - mn0);
            float p12 = __expf(S[2*kcs+1][2] - mn1), p13 = __expf(S[2*kcs+1][3] - mn1);
            ls0 += p00 + p01 + p10 + p11;
            ls1 += p02 + p03 + p12 + p13;
            split2(p00, p01, Ph[kcs][0], Pl[kcs][0]);
            split2(p02, p03, Ph[kcs][1], Pl[kcs][1]);
            split2(p10, p11, Ph[kcs][2], Pl[kcs][2]);
            split2(p12, p13, Ph[kcs][3], Pl[kcs][3]);
        }
        ls0 += __shfl_xor_sync(0xffffffffu, ls0, 1);
        ls0 += __shfl_xor_sync(0xffffffffu, ls0, 2);
        ls1 += __shfl_xor_sync(0xffffffffu, ls1, 1);
        ls1 += __shfl_xor_sync(0xffffffffu, ls1, 2);
        l0 = l0 * corr0 + ls0;
        l1 = l1 * corr1 + ls1;

        #pragma unroll
        for (int dt = 0; dt < 8; dt++) {
            O[dt][0] *= corr0; O[dt][1] *= corr0;
            O[dt][2] *= corr1; O[dt][3] *= corr1;
        }

        #pragma unroll
        for (int kcs = 0; kcs < 4; kcs++) {
            #pragma unroll
            for (int dp = 0; dp < 4; dp++) {
                int rowB = dp * 16 + (lane & 7) + ((lane >> 4) << 3);
                uint32_t colB = (uint32_t)(kcs * 32 + ((lane >> 3) & 1) * 16);
                uint32_t off = (uint32_t)(rowB * 128) + colB;
                uint32_t sw  = off ^ ((off >> 3) & 0x70);
                uint32_t vh[4], vl[4];
                ldm_x4(vh, base + 16384 + sw);
                ldm_x4(vl, base + 24576 + sw);
                mma_bf16(O[2*dp],   Ph[kcs], &vh[0]);
                mma_bf16(O[2*dp],   Ph[kcs], &vl[0]);
                mma_bf16(O[2*dp],   Pl[kcs], &vh[0]);
                mma_bf16(O[2*dp+1], Ph[kcs], &vh[2]);
                mma_bf16(O[2*dp+1], Ph[kcs], &vl[2]);
                mma_bf16(O[2*dp+1], Pl[kcs], &vh[2]);
            }
        }
        __syncthreads();
    }

    float il0 = 1.0f / l0, il1 = 1.0f / l1;
    int grow0 = b * 2048 + qt * 64 + qrow0;
    int grow1 = grow0 + 8;
    #pragma unroll
    for (int dt = 0; dt < 8; dt++) {
        int d = dt * 8 + (lane & 3) * 2;
        uint32_t hi, lo;
        split2(O[dt][0] * il0, O[dt][1] * il0, hi, lo);
        *(uint32_t*)(ohi + (size_t)grow0 * 512 + hh * 64 + d) = hi;
        *(uint32_t*)(olo + (size_t)grow0 * 512 + hh * 64 + d) = lo;
        split2(O[dt][2] * il1, O[dt][3] * il1, hi, lo);
        *(uint32_t*)(ohi + (size_t)grow1 * 512 + hh * 64 + d) = hi;
        *(uint32_t*)(olo + (size_t)grow1 * 512 + hh * 64 + d) = lo;
    }
}

// ---------------- PDL launch helper -------------------------------------------
template <typename... KArgs, typename... Args>
static void launch_pdl(void (*kern)(KArgs...), dim3 grid, dim3 block,
                       size_t smem, Args... args)
{
    cudaLaunchConfig_t cfg = {};
    cfg.gridDim = grid;
    cfg.blockDim = block;
    cfg.dynamicSmemBytes = smem;
    cudaLaunchAttribute at[1];
    at[0].id = cudaLaunchAttributeProgrammaticStreamSerialization;
    at[0].val.programmaticStreamSerializationAllowed = 1;
    cfg.attrs = at;
    cfg.numAttrs = 1;
    cudaLaunchKernelEx(&cfg, kern, static_cast<KArgs>(args)...);
}

// ---------------- launch orchestration ---------------------------------------
extern "C" void kernel_launch(void* const* d_in, const int* in_sizes, int n_in,
                              void* d_out, int out_size)
{
    const int*   x      = (const int*)  d_in[0];
    const float* emb    = (const float*)d_in[1];
    const float* ln1_s  = (const float*)d_in[2];
    const float* ln1_b  = (const float*)d_in[3];
    const float* qkv_w  = (const float*)d_in[4];
    const float* qkv_b  = (const float*)d_in[5];
    const float* afc_w  = (const float*)d_in[6];
    const float* afc_b  = (const float*)d_in[7];
    const float* ln2_s  = (const float*)d_in[8];
    const float* ln2_b  = (const float*)d_in[9];
    const float* ff_w1  = (const float*)d_in[10];
    const float* ff_b1  = (const float*)d_in[11];
    const float* ff_w2  = (const float*)d_in[12];
    const float* ff_b2  = (const float*)d_in[13];
    const float* lnf_s  = (const float*)d_in[14];
    const float* lnf_b  = (const float*)d_in[15];
    const float* fc_w   = (const float*)d_in[16];
    const float* fc_b   = (const float*)d_in[17];
    float* out = (float*)d_out;

    float *h;
    __nv_bfloat16 *ahi, *alo, *fhi, *flo, *qkhi, *qklo, *whi, *wlo;
    cudaGetSymbolAddress((void**)&h,    g_h);
    cudaGetSymbolAddress((void**)&ahi,  g_ahi);
    cudaGetSymbolAddress((void**)&alo,  g_alo);
    cudaGetSymbolAddress((void**)&fhi,  g_fhi);
    cudaGetSymbolAddress((void**)&flo,  g_flo);
    cudaGetSymbolAddress((void**)&qkhi, g_qkhi);
    cudaGetSymbolAddress((void**)&qklo, g_qklo);
    cudaGetSymbolAddress((void**)&whi,  g_whi);
    cudaGetSymbolAddress((void**)&wlo,  g_wlo);

    cudaFuncSetAttribute(gemm_tc, cudaFuncAttributeMaxDynamicSharedMemorySize, GEMM_SMEM);
    cudaFuncSetAttribute(attn_tc, cudaFuncAttributeMaxDynamicSharedMemorySize, ATTN_SMEM);

    // ---- weight prep: batched over layers, 5 launches total ----
    launch_pdl(wprep_kernel, dim3(1536/64, 512/64, NLAYER), dim3(256), 0,
        qkv_w, whi + W_OFF_QKV, wlo + W_OFF_QKV, 512, 1536,
        (size_t)512*1536, (size_t)W_LSTRIDE);
    launch_pdl(wprep_kernel, dim3(512/64, 512/64, NLAYER), dim3(256), 0,
        afc_w, whi + W_OFF_AFC, wlo + W_OFF_AFC, 512, 512,
        (size_t)512*512, (size_t)W_LSTRIDE);
    launch_pdl(wprep_kernel, dim3(2048/64, 512/64, NLAYER), dim3(256), 0,
        ff_w1, whi + W_OFF_FF1, wlo + W_OFF_FF1, 512, 2048,
        (size_t)512*2048, (size_t)W_LSTRIDE);
    launch_pdl(wprep_kernel, dim3(512/64, 2048/64, NLAYER), dim3(256), 0,
        ff_w2, whi + W_OFF_FF2, wlo + W_OFF_FF2, 2048, 512,
        (size_t)2048*512, (size_t)W_LSTRIDE);
    launch_pdl(wprep_kernel, dim3(32000/64, 512/64, 1), dim3(256), 0,
        fc_w, whi + W_OFF_FC, wlo + W_OFF_FC, 512, 32000, (size_t)0, (size_t)0);

    launch_pdl(embed_kernel, dim3(M_ROWS), dim3(256), 0, x, emb, h);

    for (int l = 0; l < NLAYER; l++) {
        launch_pdl(ln_split_kernel, dim3(M_ROWS), dim3(128), 0,
            h, ln1_s + l*D_MODEL, ln1_b + l*D_MODEL, ahi, alo);
        // qkv (scatter mode)
        launch_pdl(gemm_tc, dim3(32, 24), dim3(256), (size_t)GEMM_SMEM,
            ahi, alo, whi + l*W_LSTRIDE + W_OFF_QKV, wlo + l*W_LSTRIDE + W_OFF_QKV,
            qkv_b + (size_t)l*1536, (const float*)nullptr, (float*)nullptr,
            qkhi, qklo, M_ROWS, 1536, 512, 2);
        // attention -> ahi/alo
        launch_pdl(attn_tc, dim3(32, NHEAD, BATCH), dim3(128), (size_t)ATTN_SMEM,
            qkhi, qklo, ahi, alo);
        // h = h + att @ afc_w + afc_b
        launch_pdl(gemm_tc, dim3(32, 8), dim3(256), (size_t)GEMM_SMEM,
            ahi, alo, whi + l*W_LSTRIDE + W_OFF_AFC, wlo + l*W_LSTRIDE + W_OFF_AFC,
            afc_b + (size_t)l*512, h, h,
            (__nv_bfloat16*)nullptr, (__nv_bfloat16*)nullptr, M_ROWS, 512, 512, 0);
        launch_pdl(ln_split_kernel, dim3(M_ROWS), dim3(128), 0,
            h, ln2_s + l*D_MODEL, ln2_b + l*D_MODEL, ahi, alo);
        // ff = gelu(...) -> fhi/flo (split mode)
        launch_pdl(gemm_tc, dim3(32, 32), dim3(256), (size_t)GEMM_SMEM,
            ahi, alo, whi + l*W_LSTRIDE + W_OFF_FF1, wlo + l*W_LSTRIDE + W_OFF_FF1,
            ff_b1 + (size_t)l*2048, (const float*)nullptr, (float*)nullptr,
            fhi, flo, M_ROWS, 2048, 512, 1);
        // h = h + ff @ ff_w2 + ff_b2
        launch_pdl(gemm_tc, dim3(32, 8), dim3(256), (size_t)GEMM_SMEM,
            fhi, flo, whi + l*W_LSTRIDE + W_OFF_FF2, wlo + l*W_LSTRIDE + W_OFF_FF2,
            ff_b2 + (size_t)l*512, h, h,
            (__nv_bfloat16*)nullptr, (__nv_bfloat16*)nullptr, M_ROWS, 512, 2048, 0);
    }

    launch_pdl(ln_split_kernel, dim3(M_ROWS), dim3(128), 0,
        h, lnf_s, lnf_b, ahi, alo);
    launch_pdl(gemm_tc, dim3(32, 500), dim3(256), (size_t)GEMM_SMEM,
        ahi, alo, whi + W_OFF_FC, wlo + W_OFF_FC,
        fc_b, (const float*)nullptr, out,
        (__nv_bfloat16*)nullptr, (__nv_bfloat16*)nullptr, M_ROWS, VOCAB, 512, 0);
}

// round 16
// speedup vs baseline: 1.0204x; 1.0004x over previous
#include <cuda_runtime.h>
#include <cuda_bf16.h>
#include <cstdint>
#include <stdint.h>
#include <math.h>

#define D_MODEL 512
#define NHEAD   8
#define DHEAD   64
#define NLAYER  8
#define FF_DIM  2048
#define VOCAB   32000
#define BATCH   2
#define SEQ     2048
#define M_ROWS  (BATCH*SEQ)   // 4096

// ---------------- scratch (static __device__ globals; no allocs allowed) ----
__device__ float g_h[M_ROWS * D_MODEL];                  // residual stream fp32

__device__ __nv_bfloat16 g_ahi[M_ROWS * D_MODEL];        // ln out / attn out
__device__ __nv_bfloat16 g_alo[M_ROWS * D_MODEL];
__device__ __nv_bfloat16 g_fhi[M_ROWS * FF_DIM];         // ff1 out
__device__ __nv_bfloat16 g_flo[M_ROWS * FF_DIM];

// q/k/vt packed: Q[BH,T,DH] @0, K[BH,T,DH] @2097152, Vt[BH,DH,T] @4194304
#define QK_KOFF 2097152
#define QK_VOFF 4194304
__device__ __nv_bfloat16 g_qkhi[6291456];
__device__ __nv_bfloat16 g_qklo[6291456];

// transposed weights, bf16 hi/lo.
#define W_LSTRIDE 3145728ULL
#define W_OFF_QKV 0ULL
#define W_OFF_AFC 786432ULL
#define W_OFF_FF1 1048576ULL
#define W_OFF_FF2 2097152ULL
#define W_OFF_FC  (8ULL * W_LSTRIDE)
#define W_TOTAL   (W_OFF_FC + 32000ULL * 512ULL)
__device__ __nv_bfloat16 g_whi[W_TOTAL];
__device__ __nv_bfloat16 g_wlo[W_TOTAL];

// PDL entry sync: wait for upstream grid's writes before reading anything
// that depends on the immediately preceding kernel.
__device__ __forceinline__ void pdl_wait() {
#if defined(__CUDA_ARCH__) && (__CUDA_ARCH__ >= 900)
    cudaGridDependencySynchronize();
#endif
}

// ---------------- PTX helpers (sm_80-compatible only) ------------------------
__device__ __forceinline__ uint32_t smem_u32(const void* p) {
    uint32_t a;
    asm("{ .reg .u64 t; cvta.to.shared.u64 t, %1; cvt.u32.u64 %0, t; }"
        : "=r"(a) : "l"(p));
    return a;
}

__device__ __forceinline__ void cp_async16(uint32_t saddr, const void* gaddr) {
    asm volatile("cp.async.cg.shared.global [%0], [%1], 16;"
                 :: "r"(saddr), "l"(gaddr));
}

__device__ __forceinline__ void ldm_x4(uint32_t* r, uint32_t addr) {
    asm volatile("ldmatrix.sync.aligned.m8n8.x4.shared.b16 {%0,%1,%2,%3}, [%4];"
                 : "=r"(r[0]), "=r"(r[1]), "=r"(r[2]), "=r"(r[3]) : "r"(addr));
}

__device__ __forceinline__ void mma_bf16(float* c, const uint32_t* a, const uint32_t* b) {
    asm volatile(
        "mma.sync.aligned.m16n8k16.row.col.f32.bf16.bf16.f32 "
        "{%0,%1,%2,%3}, {%4,%5,%6,%7}, {%8,%9}, {%0,%1,%2,%3};"
        : "+f"(c[0]), "+f"(c[1]), "+f"(c[2]), "+f"(c[3])
        : "r"(a[0]), "r"(a[1]), "r"(a[2]), "r"(a[3]), "r"(b[0]), "r"(b[1]));
}

// pack two floats into bf16x2 hi reg + residual lo reg
__device__ __forceinline__ void split2(float x, float y, uint32_t& hi, uint32_t& lo) {
    __nv_bfloat16 hx = __float2bfloat16(x), hy = __float2bfloat16(y);
    __nv_bfloat162 H{hx, hy};
    __nv_bfloat162 L{__float2bfloat16(x - __bfloat162float(hx)),
                     __float2bfloat16(y - __bfloat162float(hy))};
    hi = *reinterpret_cast<uint32_t*>(&H);
    lo = *reinterpret_cast<uint32_t*>(&L);
}

// ---------------- embedding + positional encoding ---------------------------
__global__ void embed_kernel(const int* __restrict__ x,
                             const float* __restrict__ emb,
                             float* __restrict__ h)
{
    pdl_wait();
    int row = blockIdx.x;
    int t   = row % SEQ;
    int tok = x[row];
    int i   = threadIdx.x;
    float f = expf((float)(2 * i) * (-9.210340371976184f / 512.0f));
    float ang = (float)t * f;
    float s, c;
    sincosf(ang, &s, &c);
    const float* e = emb + (size_t)tok * D_MODEL;
    float* hp = h + (size_t)row * D_MODEL;
    hp[2 * i]     = e[2 * i]     + s;
    hp[2 * i + 1] = e[2 * i + 1] + c;
}

// ---------------- layernorm -> bf16 hi/lo split ------------------------------
__global__ void ln_split_kernel(const float* __restrict__ x,
                                const float* __restrict__ scale,
                                const float* __restrict__ bias,
                                __nv_bfloat16* __restrict__ yhi,
                                __nv_bfloat16* __restrict__ ylo)
{
    pdl_wait();
    int row = blockIdx.x;
    int tid = threadIdx.x;
    const float4* xr = (const float4*)(x + (size_t)row * D_MODEL);
    float4 v = xr[tid];
    float s  = v.x + v.y + v.z + v.w;
    float sq = v.x*v.x + v.y*v.y + v.z*v.z + v.w*v.w;
    #pragma unroll
    for (int o = 16; o > 0; o >>= 1) {
        s  += __shfl_xor_sync(0xffffffffu, s,  o);
        sq += __shfl_xor_sync(0xffffffffu, sq, o);
    }
    __shared__ float ss[4], ssq[4];
    int wid = tid >> 5, lane = tid & 31;
    if (lane == 0) { ss[wid] = s; ssq[wid] = sq; }
    __syncthreads();
    s  = ss[0]  + ss[1]  + ss[2]  + ss[3];
    sq = ssq[0] + ssq[1] + ssq[2] + ssq[3];
    float mu  = s * (1.0f / D_MODEL);
    float var = sq * (1.0f / D_MODEL) - mu * mu;
    float inv = rsqrtf(var + 1e-5f);
    float4 sc = ((const float4*)scale)[tid];
    float4 bi = ((const float4*)bias)[tid];
    float o0 = (v.x - mu) * inv * sc.x + bi.x;
    float o1 = (v.y - mu) * inv * sc.y + bi.y;
    float o2 = (v.z - mu) * inv * sc.z + bi.z;
    float o3 = (v.w - mu) * inv * sc.w + bi.w;
    uint32_t h0, l0, h1, l1;
    split2(o0, o1, h0, l0);
    split2(o2, o3, h1, l1);
    uint32_t* ph = (uint32_t*)(yhi + (size_t)row * D_MODEL);
    uint32_t* pl = (uint32_t*)(ylo + (size_t)row * D_MODEL);
    ph[tid*2] = h0; ph[tid*2+1] = h1;
    pl[tid*2] = l0; pl[tid*2+1] = l1;
}

// ---------------- weight transpose + split (batched over layers) -------------
// W[K,N] (fp32) -> Wt hi/lo [N,K] bf16.  64x64 tiles, 256 threads.
__global__ __launch_bounds__(256)
void wprep_kernel(const float* __restrict__ W,
                  __nv_bfloat16* __restrict__ hi,
                  __nv_bfloat16* __restrict__ lo,
                  int K, int N, size_t wstride, size_t ostride)
{
    pdl_wait();
    __shared__ float t[64][65];
    const float* Wl = W + (size_t)blockIdx.z * wstride;
    int n0 = blockIdx.x * 64, k0 = blockIdx.y * 64;
    int tid = threadIdx.x;
    #pragma unroll
    for (int j = 0; j < 4; j++) {
        int idx = tid + j * 256;
        int kk = idx >> 4;
        int c4 = idx & 15;
        float4 v = *(const float4*)&Wl[(size_t)(k0 + kk) * N + n0 + c4 * 4];
        t[kk][c4*4+0] = v.x; t[kk][c4*4+1] = v.y;
        t[kk][c4*4+2] = v.z; t[kk][c4*4+3] = v.w;
    }
    __syncthreads();
    int tx = tid & 31, ty = tid >> 5;
    size_t obase = (size_t)blockIdx.z * ostride;
    #pragma unroll
    for (int j = 0; j < 8; j++) {
        int nl = ty + j * 8;
        float v0 = t[tx*2][nl], v1 = t[tx*2+1][nl];
        uint32_t h2, l2;
        split2(v0, v1, h2, l2);
        size_t o = obase + (size_t)(n0 + nl) * K + k0 + tx * 2;
        *(uint32_t*)(hi + o) = h2;
        *(uint32_t*)(lo + o) = l2;
    }
}

// ---------------- HMMA bf16x3 GEMM (256 thr, 8 warps 4x2, BM128xBN64) --------
// 2 CTAs/SM (96KB smem), 2-stage cp.async pipeline (issue-then-wait).
// PDL prologue: chunk-0 B (weights, upstream-complete) issued BEFORE the
// grid-dependency sync; A (fresh activations) issued after.
// mode 0: C fp32 = [res +] A@W + bias
// mode 1: Ohi/Olo bf16 = split(gelu(A@W + bias))
// mode 2: scatter q/k/vt hi/lo from A@W + bias
#define CHUNK_K 64
#define STAGE_BYTES 49152
#define T_AHI 0
#define T_ALO 16384
#define T_BHI 32768
#define T_BLO 40960
#define GEMM_SMEM (2*STAGE_BYTES)

__device__ __forceinline__ void store_qkv(int row, int col, float v0, float v1,
                                          __nv_bfloat16* Ohi, __nv_bfloat16* Olo)
{
    int sect = col >> 9;
    int hh = (col >> 6) & 7;
    int d = col & 63;
    int bb = row >> 11, tt = row & 2047;
    int bh = bb * 8 + hh;
    uint32_t hi, lo;
    split2(v0, v1, hi, lo);
    if (sect < 2) {
        size_t off = (size_t)sect * QK_KOFF + ((size_t)bh * 2048 + tt) * 64 + d;
        *(uint32_t*)(Ohi + off) = hi;
        *(uint32_t*)(Olo + off) = lo;
    } else {
        size_t off = QK_VOFF + ((size_t)bh * 64 + d) * 2048 + tt;
        __nv_bfloat162 H = *reinterpret_cast<__nv_bfloat162*>(&hi);
        __nv_bfloat162 L = *reinterpret_cast<__nv_bfloat162*>(&lo);
        Ohi[off] = H.x; Ohi[off + 2048] = H.y;
        Olo[off] = L.x; Olo[off + 2048] = L.y;
    }
}

__global__ __launch_bounds__(256, 2)
void gemm_tc(const __nv_bfloat16* __restrict__ Ahi, const __nv_bfloat16* __restrict__ Alo,
             const __nv_bfloat16* __restrict__ Bhi, const __nv_bfloat16* __restrict__ Blo,
             const float* __restrict__ bias, const float* __restrict__ res,
             float* __restrict__ C, __nv_bfloat16* __restrict__ Ohi,
             __nv_bfloat16* __restrict__ Olo, int M, int N, int K, int mode)
{
    extern __shared__ char smem[];
    uint32_t sb = smem_u32(smem);
    int tid = threadIdx.x, lane = tid & 31, wid = tid >> 5;
    int bm = blockIdx.x * 128, bn = blockIdx.y * 64;   // bm fast: L2 B-tile reuse
    int wm = wid >> 1, wn = wid & 1;       // 4 x 2 warp grid, warp tile 32x32

    float acc[2][4][4];
    #pragma unroll
    for (int i = 0; i < 2; i++)
        #pragma unroll
        for (int j = 0; j < 4; j++)
            #pragma unroll
            for (int k = 0; k < 4; k++) acc[i][j][k] = 0.0f;

    int nch = K / CHUNK_K;

    auto issue_A = [&](int c, int s) {
        uint32_t base = sb + s * STAGE_BYTES;
        int k0 = c * CHUNK_K;
        #pragma unroll
        for (int i = 0; i < 4; i++) {
            int idx = tid + i * 256;
            int r = idx >> 3, q = idx & 7;
            uint32_t off = (uint32_t)(r * 128 + q * 16);
            uint32_t sw  = off ^ ((off >> 3) & 0x70);
            cp_async16(base + T_AHI + sw, Ahi + (size_t)(bm + r) * K + k0 + q * 8);
            cp_async16(base + T_ALO + sw, Alo + (size_t)(bm + r) * K + k0 + q * 8);
        }
    };
    auto issue_B = [&](int c, int s) {
        uint32_t base = sb + s * STAGE_BYTES;
        int k0 = c * CHUNK_K;
        #pragma unroll
        for (int i = 0; i < 2; i++) {
            int idx = tid + i * 256;
            int r = idx >> 3, q = idx & 7;
            uint32_t off = (uint32_t)(r * 128 + q * 16);
            uint32_t sw  = off ^ ((off >> 3) & 0x70);
            cp_async16(base + T_BHI + sw, Bhi + (size_t)(bn + r) * K + k0 + q * 8);
            cp_async16(base + T_BLO + sw, Blo + (size_t)(bn + r) * K + k0 + q * 8);
        }
    };

    // PDL prologue: weights (B) for chunk 0 are independent of the immediate
    // predecessor — issue them BEFORE the dependency sync to overlap its tail.
    issue_B(0, 0);
    asm volatile("cp.async.commit_group;" ::: "memory");   // G0 = B(0)
    pdl_wait();
    issue_A(0, 0);
    asm volatile("cp.async.commit_group;" ::: "memory");   // G1 = A(0)

    for (int c = 0; c < nch; c++) {
        int s = c & 1;
        if (c + 1 < nch) {
            issue_A(c + 1, s ^ 1);
            issue_B(c + 1, s ^ 1);
            asm volatile("cp.async.commit_group;" ::: "memory");
            asm volatile("cp.async.wait_group 1;" ::: "memory");  // chunk c fully in
        } else {
            asm volatile("cp.async.wait_group 0;" ::: "memory");
        }
        __syncthreads();

        uint32_t base = sb + s * STAGE_BYTES;
        int rowA  = wm * 32 + (lane & 15);
        int rowB  = wn * 32 + (lane & 7) + ((lane >> 4) << 3);
        #pragma unroll
        for (int ks = 0; ks < 4; ks++) {
            uint32_t ah[2][4], al[2][4], bh[4][2], bl[4][2];
            uint32_t colA = (uint32_t)(ks * 32 + ((lane >> 4) & 1) * 16);
            uint32_t colB = (uint32_t)(ks * 32 + ((lane >> 3) & 1) * 16);
            #pragma unroll
            for (int mt = 0; mt < 2; mt++) {
                uint32_t off = (uint32_t)((rowA + mt * 16) * 128) + colA;
                uint32_t sw  = off ^ ((off >> 3) & 0x70);
                ldm_x4(ah[mt], base + T_AHI + sw);
                ldm_x4(al[mt], base + T_ALO + sw);
            }
            #pragma unroll
            for (int p = 0; p < 2; p++) {
                uint32_t off = (uint32_t)((rowB + p * 16) * 128) + colB;
                uint32_t sw  = off ^ ((off >> 3) & 0x70);
                uint32_t t[4];
                ldm_x4(t, base + T_BHI + sw);
                bh[2*p][0] = t[0]; bh[2*p][1] = t[1];
                bh[2*p+1][0] = t[2]; bh[2*p+1][1] = t[3];
                ldm_x4(t, base + T_BLO + sw);
                bl[2*p][0] = t[0]; bl[2*p][1] = t[1];
                bl[2*p+1][0] = t[2]; bl[2*p+1][1] = t[3];
            }
            #pragma unroll
            for (int mt = 0; mt < 2; mt++)
                #pragma unroll
                for (int nt = 0; nt < 4; nt++) {
                    mma_bf16(acc[mt][nt], ah[mt], bh[nt]);
                    mma_bf16(acc[mt][nt], ah[mt], bl[nt]);
                    mma_bf16(acc[mt][nt], al[mt], bh[nt]);
                }
        }
        __syncthreads();
    }

    #pragma unroll
    for (int mt = 0; mt < 2; mt++) {
        #pragma unroll
        for (int nt = 0; nt < 4; nt++) {
            int row = bm + wm * 32 + mt * 16 + (lane >> 2);
            int col = bn + wn * 32 + nt * 8 + (lane & 3) * 2;
            float* a = acc[mt][nt];
            float2 b2 = *(const float2*)(bias + col);
            float v0 = a[0] + b2.x, v1 = a[1] + b2.y;
            float v2 = a[2] + b2.x, v3 = a[3] + b2.y;
            if (mode == 0) {
                if (res) {
                    float2 r0 = *(const float2*)(res + (size_t)row * N + col);
                    float2 r1 = *(const float2*)(res + (size_t)(row + 8) * N + col);
                    v0 += r0.x; v1 += r0.y; v2 += r1.x; v3 += r1.y;
                }
                *(float2*)(C + (size_t)row * N + col)       = make_float2(v0, v1);
                *(float2*)(C + (size_t)(row + 8) * N + col) = make_float2(v2, v3);
            } else if (mode == 1) {
                v0 = 0.5f * v0 * (1.0f + erff(v0 * 0.7071067811865475f));
                v1 = 0.5f * v1 * (1.0f + erff(v1 * 0.7071067811865475f));
                v2 = 0.5f * v2 * (1.0f + erff(v2 * 0.7071067811865475f));
                v3 = 0.5f * v3 * (1.0f + erff(v3 * 0.7071067811865475f));
                uint32_t hi, lo;
                split2(v0, v1, hi, lo);
                *(uint32_t*)(Ohi + (size_t)row * N + col) = hi;
                *(uint32_t*)(Olo + (size_t)row * N + col) = lo;
                split2(v2, v3, hi, lo);
                *(uint32_t*)(Ohi + (size_t)(row + 8) * N + col) = hi;
                *(uint32_t*)(Olo + (size_t)(row + 8) * N + col) = lo;
            } else {
                store_qkv(row,     col, v0, v1, Ohi, Olo);
                store_qkv(row + 8, col, v2, v3, Ohi, Olo);
            }
        }
    }
}

// ---------------- HMMA flash attention ---------------------------------------
// grid (32 qtiles, 8 heads, 2 batch), 128 threads (4 warps, 16 q-rows each).
// smem: 2 KV stages x 32KB; Q tile ALIASED into stage 1.  64KB -> 3 CTAs/SM.
#define AS_STAGE 0
#define AS_Q     32768              // = stage 1 base (aliased)
#define AS_QLO   (32768 + 8192)
#define ATTN_SMEM 65536

__global__ __launch_bounds__(128, 3)
void attn_tc(const __nv_bfloat16* __restrict__ qk_hi,
             const __nv_bfloat16* __restrict__ qk_lo,
             __nv_bfloat16* __restrict__ ohi, __nv_bfloat16* __restrict__ olo)
{
    pdl_wait();
    extern __shared__ char smem[];
    uint32_t sb = smem_u32(smem);
    int qt = 31 - blockIdx.x;          // big tiles first (less tail)
    int hh = blockIdx.y, b = blockIdx.z;
    int tid = threadIdx.x, lane = tid & 31, warp = tid >> 5;
    int bh = b * 8 + hh;

    const __nv_bfloat16* qhi  = qk_hi;
    const __nv_bfloat16* qlo  = qk_lo;
    const __nv_bfloat16* khi  = qk_hi + QK_KOFF;
    const __nv_bfloat16* klo  = qk_lo + QK_KOFF;
    const __nv_bfloat16* vthi = qk_hi + QK_VOFF;
    const __nv_bfloat16* vtlo = qk_lo + QK_VOFF;

    #pragma unroll
    for (int i = 0; i < 4; i++) {
        int idx = tid + i * 128;
        int r = idx >> 3, c8 = idx & 7;
        uint32_t off = (uint32_t)(r * 128 + c8 * 16);
        uint32_t sw  = off ^ ((off >> 3) & 0x70);
        cp_async16(sb + AS_Q   + sw, qhi + ((size_t)bh * 2048 + qt * 64 + r) * 64 + c8 * 8);
        cp_async16(sb + AS_QLO + sw, qlo + ((size_t)bh * 2048 + qt * 64 + r) * 64 + c8 * 8);
    }
    asm volatile("cp.async.commit_group;" ::: "memory");

    auto load_kv = [&](int kt, int s) {
        uint32_t base = sb + AS_STAGE + s * 32768;
        #pragma unroll
        for (int i = 0; i < 4; i++) {
            int idx = tid + i * 128;
            int r = idx >> 3, c8 = idx & 7;
            uint32_t off = (uint32_t)(r * 128 + c8 * 16);
            uint32_t sw  = off ^ ((off >> 3) & 0x70);
            cp_async16(base + sw,         khi  + ((size_t)bh * 2048 + kt * 64 + r) * 64 + c8 * 8);
            cp_async16(base + 8192 + sw,  klo  + ((size_t)bh * 2048 + kt * 64 + r) * 64 + c8 * 8);
            cp_async16(base + 16384 + sw, vthi + ((size_t)bh * 64 + r) * 2048 + kt * 64 + c8 * 8);
            cp_async16(base + 24576 + sw, vtlo + ((size_t)bh * 64 + r) * 2048 + kt * 64 + c8 * 8);
        }
        asm volatile("cp.async.commit_group;" ::: "memory");
    };

    load_kv(0, 0);                      // stage 0 (does not touch Q alias)
    asm volatile("cp.async.wait_group 1;" ::: "memory");   // Q arrived
    __syncthreads();

    uint32_t Qh[4][4], Ql[4][4];
    {
        int rowA = warp * 16 + (lane & 15);
        #pragma unroll
        for (int kc = 0; kc < 4; kc++) {
            uint32_t colA = (uint32_t)(kc * 32 + ((lane >> 4) & 1) * 16);
            uint32_t off = (uint32_t)(rowA * 128) + colA;
            uint32_t sw  = off ^ ((off >> 3) & 0x70);
            ldm_x4(Qh[kc], sb + AS_Q   + sw);
            ldm_x4(Ql[kc], sb + AS_QLO + sw);
        }
    }
    __syncthreads();   // all warps done reading Q before stage 1 (alias) is written

    float O[8][4];
    #pragma unroll
    for (int i = 0; i < 8; i++)
        #pragma unroll
        for (int j = 0; j < 4; j++) O[i][j] = 0.0f;
    float m0 = -1e30f, m1 = -1e30f, l0 = 0.0f, l1 = 0.0f;

    int r0 = lane >> 2;
    int qrow0 = warp * 16 + r0, qrow1 = qrow0 + 8;

    for (int kt = 0; kt <= qt; kt++) {
        int s = kt & 1;
        if (kt < qt) {
            load_kv(kt + 1, s ^ 1);
            asm volatile("cp.async.wait_group 1;" ::: "memory");
        } else {
            asm volatile("cp.async.wait_group 0;" ::: "memory");
        }
        __syncthreads();
        uint32_t base = sb + AS_STAGE + s * 32768;

        float S[8][4];
        #pragma unroll
        for (int i = 0; i < 8; i++)
            #pragma unroll
            for (int j = 0; j < 4; j++) S[i][j] = 0.0f;

        #pragma unroll
        for (int kc = 0; kc < 4; kc++) {
            #pragma unroll
            for (int sp = 0; sp < 4; sp++) {
                int rowB = sp * 16 + (lane & 7) + ((lane >> 4) << 3);
                uint32_t colB = (uint32_t)(kc * 32 + ((lane >> 3) & 1) * 16);
                uint32_t off = (uint32_t)(rowB * 128) + colB;
                uint32_t sw  = off ^ ((off >> 3) & 0x70);
                uint32_t kh[4], kl[4];
                ldm_x4(kh, base + sw);
                ldm_x4(kl, base + 8192 + sw);
                mma_bf16(S[2*sp],   Qh[kc], &kh[0]);
                mma_bf16(S[2*sp],   Qh[kc], &kl[0]);
                mma_bf16(S[2*sp],   Ql[kc], &kh[0]);
                mma_bf16(S[2*sp+1], Qh[kc], &kh[2]);
                mma_bf16(S[2*sp+1], Qh[kc], &kl[2]);
                mma_bf16(S[2*sp+1], Ql[kc], &kh[2]);
            }
        }

        bool diag = (kt == qt);
        float mx0 = -1e30f, mx1 = -1e30f;
        #pragma unroll
        for (int nt = 0; nt < 8; nt++) {
            int c0 = nt * 8 + (lane & 3) * 2;
            float v0 = S[nt][0] * 0.125f, v1 = S[nt][1] * 0.125f;
            float v2 = S[nt][2] * 0.125f, v3 = S[nt][3] * 0.125f;
            if (diag) {
                if (c0     > qrow0) v0 = -1e30f;
                if (c0 + 1 > qrow0) v1 = -1e30f;
                if (c0     > qrow1) v2 = -1e30f;
                if (c0 + 1 > qrow1) v3 = -1e30f;
            }
            S[nt][0] = v0; S[nt][1] = v1; S[nt][2] = v2; S[nt][3] = v3;
            mx0 = fmaxf(mx0, fmaxf(v0, v1));
            mx1 = fmaxf(mx1, fmaxf(v2, v3));
        }
        mx0 = fmaxf(mx0, __shfl_xor_sync(0xffffffffu, mx0, 1));
        mx0 = fmaxf(mx0, __shfl_xor_sync(0xffffffffu, mx0, 2));
        mx1 = fmaxf(mx1, __shfl_xor_sync(0xffffffffu, mx1, 1));
        mx1 = fmaxf(mx1, __shfl_xor_sync(0xffffffffu, mx1, 2));

        float mn0 = fmaxf(m0, mx0), mn1 = fmaxf(m1, mx1);
        float corr0 = __expf(m0 - mn0), corr1 = __expf(m1 - mn1);
        m0 = mn0; m1 = mn1;

        uint32_t Ph[4][4], Pl[4][4];
        float ls0 = 0.0f, ls1 = 0.0f;
        #pragma unroll
        for (int kcs = 0; kcs < 4; kcs++) {
            float p00 = __expf(S[2*kcs][0]   - mn0), p01 = __expf(S[2*kcs][1]   - mn0);
            float p02 = __expf(S[2*kcs][2]   - mn1), p03 = __expf(S[2*kcs][3]   - mn1);
            float p10 = __expf(S[2*kcs+1][0] - mn0), p11 = __expf(S[2*kcs+1][1] - mn0);
            float p12 = __expf(S[2*kcs+1][2] - mn1), p13 = __expf(S[2*kcs+1][3] - mn1);
            ls0 += p00 + p01 + p10 + p11;
            ls1 += p02 + p03 + p12 + p13;
            split2(p00, p01, Ph[kcs][0], Pl[kcs][0]);
            split2(p02, p03, Ph[kcs][1], Pl[kcs][1]);
            split2(p10, p11, Ph[kcs][2], Pl[kcs][2]);
            split2(p12, p13, Ph[kcs][3], Pl[kcs][3]);
        }
        ls0 += __shfl_xor_sync(0xffffffffu, ls0, 1);
        ls0 += __shfl_xor_sync(0xffffffffu, ls0, 2);
        ls1 += __shfl_xor_sync(0xffffffffu, ls1, 1);
        ls1 += __shfl_xor_sync(0xffffffffu, ls1, 2);
        l0 = l0 * corr0 + ls0;
        l1 = l1 * corr1 + ls1;

        #pragma unroll
        for (int dt = 0; dt < 8; dt++) {
            O[dt][0] *= corr0; O[dt][1] *= corr0;
            O[dt][2] *= corr1; O[dt][3] *= corr1;
        }

        #pragma unroll
        for (int kcs = 0; kcs < 4; kcs++) {
            #pragma unroll
            for (int dp = 0; dp < 4; dp++) {
                int rowB = dp * 16 + (lane & 7) + ((lane >> 4) << 3);
                uint32_t colB = (uint32_t)(kcs * 32 + ((lane >> 3) & 1) * 16);
                uint32_t off = (uint32_t)(rowB * 128) + colB;
                uint32_t sw  = off ^ ((off >> 3) & 0x70);
                uint32_t vh[4], vl[4];
                ldm_x4(vh, base + 16384 + sw);
                ldm_x4(vl, base + 24576 + sw);
                mma_bf16(O[2*dp],   Ph[kcs], &vh[0]);
                mma_bf16(O[2*dp],   Ph[kcs], &vl[0]);
                mma_bf16(O[2*dp],   Pl[kcs], &vh[0]);
                mma_bf16(O[2*dp+1], Ph[kcs], &vh[2]);
                mma_bf16(O[2*dp+1], Ph[kcs], &vl[2]);
                mma_bf16(O[2*dp+1], Pl[kcs], &vh[2]);
            }
        }
        __syncthreads();
    }

    float il0 = 1.0f / l0, il1 = 1.0f / l1;
    int grow0 = b * 2048 + qt * 64 + qrow0;
    int grow1 = grow0 + 8;
    #pragma unroll
    for (int dt = 0; dt < 8; dt++) {
        int d = dt * 8 + (lane & 3) * 2;
        uint32_t hi, lo;
        split2(O[dt][0] * il0, O[dt][1] * il0, hi, lo);
        *(uint32_t*)(ohi + (size_t)grow0 * 512 + hh * 64 + d) = hi;
        *(uint32_t*)(olo + (size_t)grow0 * 512 + hh * 64 + d) = lo;
        split2(O[dt][2] * il1, O[dt][3] * il1, hi, lo);
        *(uint32_t*)(ohi + (size_t)grow1 * 512 + hh * 64 + d) = hi;
        *(uint32_t*)(olo + (size_t)grow1 * 512 + hh * 64 + d) = lo;
    }
}

// ---------------- PDL launch helper -------------------------------------------
template <typename... KArgs, typename... Args>
static void launch_pdl(void (*kern)(KArgs...), dim3 grid, dim3 block,
                       size_t smem, Args... args)
{
    cudaLaunchConfig_t cfg = {};
    cfg.gridDim = grid;
    cfg.blockDim = block;
    cfg.dynamicSmemBytes = smem;
    cudaLaunchAttribute at[1];
    at[0].id = cudaLaunchAttributeProgrammaticStreamSerialization;
    at[0].val.programmaticStreamSerializationAllowed = 1;
    cfg.attrs = at;
    cfg.numAttrs = 1;
    cudaLaunchKernelEx(&cfg, kern, static_cast<KArgs>(args)...);
}

// ---------------- launch orchestration ---------------------------------------
extern "C" void kernel_launch(void* const* d_in, const int* in_sizes, int n_in,
                              void* d_out, int out_size)
{
    const int*   x      = (const int*)  d_in[0];
    const float* emb    = (const float*)d_in[1];
    const float* ln1_s  = (const float*)d_in[2];
    const float* ln1_b  = (const float*)d_in[3];
    const float* qkv_w  = (const float*)d_in[4];
    const float* qkv_b  = (const float*)d_in[5];
    const float* afc_w  = (const float*)d_in[6];
    const float* afc_b  = (const float*)d_in[7];
    const float* ln2_s  = (const float*)d_in[8];
    const float* ln2_b  = (const float*)d_in[9];
    const float* ff_w1  = (const float*)d_in[10];
    const float* ff_b1  = (const float*)d_in[11];
    const float* ff_w2  = (const float*)d_in[12];
    const float* ff_b2  = (const float*)d_in[13];
    const float* lnf_s  = (const float*)d_in[14];
    const float* lnf_b  = (const float*)d_in[15];
    const float* fc_w   = (const float*)d_in[16];
    const float* fc_b   = (const float*)d_in[17];
    float* out = (float*)d_out;

    float *h;
    __nv_bfloat16 *ahi, *alo, *fhi, *flo, *qkhi, *qklo, *whi, *wlo;
    cudaGetSymbolAddress((void**)&h,    g_h);
    cudaGetSymbolAddress((void**)&ahi,  g_ahi);
    cudaGetSymbolAddress((void**)&alo,  g_alo);
    cudaGetSymbolAddress((void**)&fhi,  g_fhi);
    cudaGetSymbolAddress((void**)&flo,  g_flo);
    cudaGetSymbolAddress((void**)&qkhi, g_qkhi);
    cudaGetSymbolAddress((void**)&qklo, g_qklo);
    cudaGetSymbolAddress((void**)&whi,  g_whi);
    cudaGetSymbolAddress((void**)&wlo,  g_wlo);

    cudaFuncSetAttribute(gemm_tc, cudaFuncAttributeMaxDynamicSharedMemorySize, GEMM_SMEM);
    cudaFuncSetAttribute(attn_tc, cudaFuncAttributeMaxDynamicSharedMemorySize, ATTN_SMEM);

    // ---- weight prep: batched over layers, 5 launches total ----
    launch_pdl(wprep_kernel, dim3(1536/64, 512/64, NLAYER), dim3(256), 0,
        qkv_w, whi + W_OFF_QKV, wlo + W_OFF_QKV, 512, 1536,
        (size_t)512*1536, (size_t)W_LSTRIDE);
    launch_pdl(wprep_kernel, dim3(512/64, 512/64, NLAYER), dim3(256), 0,
        afc_w, whi + W_OFF_AFC, wlo + W_OFF_AFC, 512, 512,
        (size_t)512*512, (size_t)W_LSTRIDE);
    launch_pdl(wprep_kernel, dim3(2048/64, 512/64, NLAYER), dim3(256), 0,
        ff_w1, whi + W_OFF_FF1, wlo + W_OFF_FF1, 512, 2048,
        (size_t)512*2048, (size_t)W_LSTRIDE);
    launch_pdl(wprep_kernel, dim3(512/64, 2048/64, NLAYER), dim3(256), 0,
        ff_w2, whi + W_OFF_FF2, wlo + W_OFF_FF2, 2048, 512,
        (size_t)2048*512, (size_t)W_LSTRIDE);
    launch_pdl(wprep_kernel, dim3(32000/64, 512/64, 1), dim3(256), 0,
        fc_w, whi + W_OFF_FC, wlo + W_OFF_FC, 512, 32000, (size_t)0, (size_t)0);

    launch_pdl(embed_kernel, dim3(M_ROWS), dim3(256), 0, x, emb, h);

    for (int l = 0; l < NLAYER; l++) {
        launch_pdl(ln_split_kernel, dim3(M_ROWS), dim3(128), 0,
            h, ln1_s + l*D_MODEL, ln1_b + l*D_MODEL, ahi, alo);
        // qkv (scatter mode)
        launch_pdl(gemm_tc, dim3(32, 24), dim3(256), (size_t)GEMM_SMEM,
            ahi, alo, whi + l*W_LSTRIDE + W_OFF_QKV, wlo + l*W_LSTRIDE + W_OFF_QKV,
            qkv_b + (size_t)l*1536, (const float*)nullptr, (float*)nullptr,
            qkhi, qklo, M_ROWS, 1536, 512, 2);
        // attention -> ahi/alo
        launch_pdl(attn_tc, dim3(32, NHEAD, BATCH), dim3(128), (size_t)ATTN_SMEM,
            qkhi, qklo, ahi, alo);
        // h = h + att @ afc_w + afc_b
        launch_pdl(gemm_tc, dim3(32, 8), dim3(256), (size_t)GEMM_SMEM,
            ahi, alo, whi + l*W_LSTRIDE + W_OFF_AFC, wlo + l*W_LSTRIDE + W_OFF_AFC,
            afc_b + (size_t)l*512, h, h,
            (__nv_bfloat16*)nullptr, (__nv_bfloat16*)nullptr, M_ROWS, 512, 512, 0);
        launch_pdl(ln_split_kernel, dim3(M_ROWS), dim3(128), 0,
            h, ln2_s + l*D_MODEL, ln2_b + l*D_MODEL, ahi, alo);
        // ff = gelu(...) -> fhi/flo (split mode)
        launch_pdl(gemm_tc, dim3(32, 32), dim3(256), (size_t)GEMM_SMEM,
            ahi, alo, whi + l*W_LSTRIDE + W_OFF_FF1, wlo + l*W_LSTRIDE + W_OFF_FF1,
            ff_b1 + (size_t)l*2048, (const float*)nullptr, (float*)nullptr,
            fhi, flo, M_ROWS, 2048, 512, 1);
        // h = h + ff @ ff_w2 + ff_b2
        launch_pdl(gemm_tc, dim3(32, 8), dim3(256), (size_t)GEMM_SMEM,
            fhi, flo, whi + l*W_LSTRIDE + W_OFF_FF2, wlo + l*W_LSTRIDE + W_OFF_FF2,
            ff_b2 + (size_t)l*512, h, h,
            (__nv_bfloat16*)nullptr, (__nv_bfloat16*)nullptr, M_ROWS, 512, 2048, 0);
    }

    launch_pdl(ln_split_kernel, dim3(M_ROWS), dim3(128), 0,
        h, lnf_s, lnf_b, ahi, alo);
    launch_pdl(gemm_tc, dim3(32, 500), dim3(256), (size_t)GEMM_SMEM,
        ahi, alo, whi + W_OFF_FC, wlo + W_OFF_FC,
        fc_b, (const float*)nullptr, out,
        (__nv_bfloat16*)nullptr, (__nv_bfloat16*)nullptr, M_ROWS, VOCAB, 512, 0);
}